// round 1
// baseline (speedup 1.0000x reference)
#include <cuda_runtime.h>

#define BB 8
#define LL 4096
#define DX 128
#define BL (BB*LL)

// ---------------- scratch (__device__ globals: allocation-free) ----------------
__device__ float g_v1[DX], g_u1[DX], g_u2[DX];
__device__ float g_cq[BB];          // per-batch logit offset: c·v2 + bsa·wt
__device__ float g_cconst;          // bsa1·wsat_w + wsat_b
__device__ float g_logits[BL], g_d1[BL], g_d2[BL];
__device__ float g_si[BL], g_sjc[BL];   // sjc = sj + const
__device__ float g_invZ[BL], g_S[BL];
__device__ float g_Zpart[BL*4], g_Spart[BL*4];

// ---------------- fast f(t) = exp(sigmoid(t)) ----------------
__device__ __forceinline__ float ex2a(float x){ float r; asm("ex2.approx.ftz.f32 %0,%1;":"=f"(r):"f"(x)); return r; }
__device__ __forceinline__ float rcpa(float x){ float r; asm("rcp.approx.ftz.f32 %0,%1;":"=f"(r):"f"(x)); return r; }
__device__ __forceinline__ float fsig(float t){
    const float L2E = 1.44269504088896f;
    float e = ex2a(t * -L2E);       // exp(-t)
    float s = rcpa(1.0f + e);       // sigmoid(t)
    return ex2a(s * L2E);           // exp(sigmoid(t))
}

// ---------------- kernel A: fold linear heads into vectors ----------------
__global__ void kprep(const float* __restrict__ W1, const float* __restrict__ W2,
                      const float* __restrict__ wt_w, const float* __restrict__ bsa,
                      const float* __restrict__ Wsa1, const float* __restrict__ Wsa2,
                      const float* __restrict__ wsat_w, const float* __restrict__ wsat_b,
                      const float* __restrict__ bsa1, const float* __restrict__ c)
{
    __shared__ float s_wt[DX], s_ws[DX], s_v2[DX], s_red[DX];
    int d = threadIdx.x;
    s_wt[d] = wt_w[d];
    s_ws[d] = wsat_w[d];
    __syncthreads();
    float v1=0.f, v2=0.f, u1=0.f, u2=0.f;
    #pragma unroll 4
    for (int e=0; e<DX; e++){
        v1 = fmaf(W1  [d*DX+e], s_wt[e], v1);
        v2 = fmaf(W2  [d*DX+e], s_wt[e], v2);
        u1 = fmaf(Wsa1[d*DX+e], s_ws[e], u1);
        u2 = fmaf(Wsa2[d*DX+e], s_ws[e], u2);
    }
    g_v1[d]=v1; g_u1[d]=u1; g_u2[d]=u2; s_v2[d]=v2;
    s_red[d] = bsa[d]*s_wt[d];
    __syncthreads();
    for (int o=64;o;o>>=1){ if(d<o) s_red[d]+=s_red[d+o]; __syncthreads(); }
    float bterm = s_red[0];
    __syncthreads();
    s_red[d] = bsa1[d]*s_ws[d];
    __syncthreads();
    for (int o=64;o;o>>=1){ if(d<o) s_red[d]+=s_red[d+o]; __syncthreads(); }
    if (d==0) g_cconst = s_red[0] + wsat_b[0];
    if (d < BB){
        float acc = bterm;
        for (int e=0;e<DX;e++) acc = fmaf(c[d*DX+e], s_v2[e], acc);
        g_cq[d] = acc;
    }
}

// ---------------- kernel B: per-row dots (warp per row) ----------------
__global__ void kdots(const float* __restrict__ x)
{
    int gt  = blockIdx.x*blockDim.x + threadIdx.x;
    int row = gt >> 5;
    int lane = gt & 31;
    if (row >= BL) return;
    float4 xv = ((const float4*)x)[row*32 + lane];
    float4 av = ((const float4*)g_v1)[lane];
    float4 bv = ((const float4*)g_u1)[lane];
    float4 cv = ((const float4*)g_u2)[lane];
    float s0 = xv.x*av.x + xv.y*av.y + xv.z*av.z + xv.w*av.w;
    float s1 = xv.x*bv.x + xv.y*bv.y + xv.z*bv.z + xv.w*bv.w;
    float s2 = xv.x*cv.x + xv.y*cv.y + xv.z*cv.z + xv.w*cv.w;
    #pragma unroll
    for (int o=16;o;o>>=1){
        s0 += __shfl_down_sync(0xffffffffu, s0, o);
        s1 += __shfl_down_sync(0xffffffffu, s1, o);
        s2 += __shfl_down_sync(0xffffffffu, s2, o);
    }
    if (lane==0){
        g_logits[row] = s0 + g_cq[row>>12];
        g_d1[row] = s1;
        g_d2[row] = s2;
    }
}

// ---------------- kernel C: softmax over L per batch; emit si, sjc ----------------
__global__ void ksm()
{
    int b = blockIdx.x, tid = threadIdx.x;
    __shared__ float red[256];
    const float* lg = g_logits + b*LL;
    float m = -1e30f;
    for (int i=tid;i<LL;i+=256) m = fmaxf(m, lg[i]);
    red[tid]=m; __syncthreads();
    for (int o=128;o;o>>=1){ if(tid<o) red[tid]=fmaxf(red[tid],red[tid+o]); __syncthreads(); }
    m = red[0]; __syncthreads();
    float s=0.f;
    for (int i=tid;i<LL;i+=256) s += __expf(lg[i]-m);
    red[tid]=s; __syncthreads();
    for (int o=128;o;o>>=1){ if(tid<o) red[tid]+=red[tid+o]; __syncthreads(); }
    float inv = 1.0f/red[0];
    float cc  = g_cconst;
    for (int i=tid;i<LL;i+=256){
        float p = __expf(lg[i]-m)*inv;
        g_si [b*LL+i] = p*g_d1[b*LL+i];
        g_sjc[b*LL+i] = fmaf(p, g_d2[b*LL+i], cc);
    }
}

// ---------------- kernel D: row sums Z (partial over j-tiles) ----------------
__global__ void __launch_bounds__(128) kZ()
{
    __shared__ float ssj[1024];
    int b = blockIdx.z, jt = blockIdx.y, it = blockIdx.x;
    const float* sjc = g_sjc + b*LL + jt*1024;
    for (int j=threadIdx.x;j<1024;j+=128) ssj[j]=sjc[j];
    __syncthreads();
    int i = it*128 + threadIdx.x;
    float si = g_si[b*LL+i];
    float a0=0.f,a1=0.f,a2=0.f,a3=0.f;
    #pragma unroll 2
    for (int j=0;j<1024;j+=4){
        a0 += fsig(si+ssj[j+0]);
        a1 += fsig(si+ssj[j+1]);
        a2 += fsig(si+ssj[j+2]);
        a3 += fsig(si+ssj[j+3]);
    }
    g_Zpart[(b*4+jt)*LL + i] = (a0+a1)+(a2+a3);
}

__global__ void kZfin()
{
    int g = blockIdx.x*blockDim.x + threadIdx.x;
    int b = g >> 12, il = g & (LL-1);
    float Z = g_Zpart[(b*4+0)*LL+il] + g_Zpart[(b*4+1)*LL+il]
            + g_Zpart[(b*4+2)*LL+il] + g_Zpart[(b*4+3)*LL+il];
    Z -= fsig(g_si[g] + g_sjc[g]);      // diagonal masked with -inf -> weight 0
    g_invZ[g] = 1.0f / Z;
}

// ---------------- kernel E: column sums S (partial over i-tiles) ----------------
__global__ void __launch_bounds__(128) kS()
{
    __shared__ float ssi[1024], swz[1024];
    int b = blockIdx.z, ic = blockIdx.y, jt = blockIdx.x;
    int base = b*LL + ic*1024;
    for (int k=threadIdx.x;k<1024;k+=128){ ssi[k]=g_si[base+k]; swz[k]=g_invZ[base+k]; }
    __syncthreads();
    int j = jt*128 + threadIdx.x;
    float sj = g_sjc[b*LL+j];
    float a0=0.f,a1=0.f,a2=0.f,a3=0.f;
    #pragma unroll 2
    for (int i=0;i<1024;i+=4){
        a0 = fmaf(fsig(sj+ssi[i+0]), swz[i+0], a0);
        a1 = fmaf(fsig(sj+ssi[i+1]), swz[i+1], a1);
        a2 = fmaf(fsig(sj+ssi[i+2]), swz[i+2], a2);
        a3 = fmaf(fsig(sj+ssi[i+3]), swz[i+3], a3);
    }
    g_Spart[(b*4+ic)*LL + j] = (a0+a1)+(a2+a3);
}

__global__ void kSfin()
{
    int g = blockIdx.x*blockDim.x + threadIdx.x;
    int b = g >> 12, il = g & (LL-1);
    float S = g_Spart[(b*4+0)*LL+il] + g_Spart[(b*4+1)*LL+il]
            + g_Spart[(b*4+2)*LL+il] + g_Spart[(b*4+3)*LL+il];
    S -= fsig(g_si[g] + g_sjc[g]) * g_invZ[g];   // remove diagonal term
    g_S[g] = S;
}

// ---------------- kernel F: fused ui -> FFN -> residual -> LayerNorm ----------------
__device__ __forceinline__ void fma4(float acc[4], float xs, const float4 wv){
    acc[0] = fmaf(xs, wv.x, acc[0]);
    acc[1] = fmaf(xs, wv.y, acc[1]);
    acc[2] = fmaf(xs, wv.z, acc[2]);
    acc[3] = fmaf(xs, wv.w, acc[3]);
}

__device__ __forceinline__ void gemm_tile(const float* __restrict__ ws,
                                          const float* __restrict__ in_s,
                                          int r0, int col, float acc[8][4])
{
    #pragma unroll 2
    for (int d=0; d<DX; d+=4){
        float4 w0 = *(const float4*)(ws + (d+0)*DX + col);
        float4 w1 = *(const float4*)(ws + (d+1)*DX + col);
        float4 w2 = *(const float4*)(ws + (d+2)*DX + col);
        float4 w3 = *(const float4*)(ws + (d+3)*DX + col);
        #pragma unroll
        for (int r=0;r<8;r++){
            float4 xv = *(const float4*)(in_s + (r0+r)*DX + d);
            fma4(acc[r], xv.x, w0);
            fma4(acc[r], xv.y, w1);
            fma4(acc[r], xv.z, w2);
            fma4(acc[r], xv.w, w3);
        }
    }
}

__global__ void __launch_bounds__(256) kffn(const float* __restrict__ x,
        const float* __restrict__ w1, const float* __restrict__ b1,
        const float* __restrict__ w2, const float* __restrict__ b2,
        const float* __restrict__ lng, const float* __restrict__ lnb,
        float* __restrict__ out)
{
    extern __shared__ float sm[];
    float* w1s = sm;            // 16384 floats
    float* w2s = sm + 16384;    // 16384 floats
    float* ins = sm + 32768;    // 8192 floats (64 rows x 128)
    float* hs  = sm + 40960;    // 8192 floats

    int tid = threadIdx.x;
    int lane = tid & 31, w = tid >> 5;
    int rowbase = blockIdx.x * 64;

    for (int k=tid; k<4096; k+=256){
        ((float4*)w1s)[k] = ((const float4*)w1)[k];
        ((float4*)w2s)[k] = ((const float4*)w2)[k];
    }
    const float4* xr = (const float4*)(x + (size_t)rowbase*DX);
    for (int k=tid; k<2048; k+=256){
        int r = k >> 5;                     // 32 float4 per row
        float s = g_S[rowbase + r];
        float4 v = xr[k];
        v.x*=s; v.y*=s; v.z*=s; v.w*=s;     // ui = x * S
        ((float4*)ins)[k] = v;
    }
    __syncthreads();

    int col = lane*4;
    int r0  = w*8;
    float acc[8][4];

    // stage 1: hidden = relu(ui @ W1 + b1)
    #pragma unroll
    for (int r=0;r<8;r++){ acc[r][0]=acc[r][1]=acc[r][2]=acc[r][3]=0.f; }
    gemm_tile(w1s, ins, r0, col, acc);
    {
        float4 bb = ((const float4*)b1)[lane];
        #pragma unroll
        for (int r=0;r<8;r++){
            float4 h;
            h.x = fmaxf(acc[r][0]+bb.x, 0.f);
            h.y = fmaxf(acc[r][1]+bb.y, 0.f);
            h.z = fmaxf(acc[r][2]+bb.z, 0.f);
            h.w = fmaxf(acc[r][3]+bb.w, 0.f);
            *(float4*)(hs + (r0+r)*DX + col) = h;
        }
    }
    __syncthreads();

    // stage 2: y = hidden @ W2 + b2 + ui
    #pragma unroll
    for (int r=0;r<8;r++){ acc[r][0]=acc[r][1]=acc[r][2]=acc[r][3]=0.f; }
    gemm_tile(w2s, hs, r0, col, acc);
    {
        float4 bb = ((const float4*)b2)[lane];
        #pragma unroll
        for (int r=0;r<8;r++){
            float4 resid = *(const float4*)(ins + (r0+r)*DX + col);
            float4 o;
            o.x = acc[r][0]+bb.x+resid.x;
            o.y = acc[r][1]+bb.y+resid.y;
            o.z = acc[r][2]+bb.z+resid.z;
            o.w = acc[r][3]+bb.w+resid.w;
            *(float4*)(ins + (r0+r)*DX + col) = o;   // in place, own elements
        }
    }
    __syncthreads();

    // LayerNorm (warp per row-group)
    float4 gv = ((const float4*)lng)[lane];
    float4 bv = ((const float4*)lnb)[lane];
    #pragma unroll
    for (int r=0;r<8;r++){
        float4 v = *(const float4*)(ins + (r0+r)*DX + col);
        float s = v.x+v.y+v.z+v.w;
        #pragma unroll
        for (int o=16;o;o>>=1) s += __shfl_xor_sync(0xffffffffu, s, o);
        float mu = s * (1.0f/128.0f);
        float d0=v.x-mu, d1=v.y-mu, d2=v.z-mu, d3=v.w-mu;
        float q = d0*d0+d1*d1+d2*d2+d3*d3;
        #pragma unroll
        for (int o=16;o;o>>=1) q += __shfl_xor_sync(0xffffffffu, q, o);
        float inv = rsqrtf(q*(1.0f/128.0f) + 1e-6f);
        float4 ov;
        ov.x = d0*inv*gv.x + bv.x;
        ov.y = d1*inv*gv.y + bv.y;
        ov.z = d2*inv*gv.z + bv.z;
        ov.w = d3*inv*gv.w + bv.w;
        ((float4*)(out + (size_t)(rowbase + r0 + r)*DX))[lane] = ov;
    }
}

// ---------------- launch ----------------
extern "C" void kernel_launch(void* const* d_in, const int* in_sizes, int n_in,
                              void* d_out, int out_size)
{
    const float* x     = (const float*)d_in[0];
    const float* c     = (const float*)d_in[1];
    const float* W1    = (const float*)d_in[2];
    const float* W2    = (const float*)d_in[3];
    const float* wt_w  = (const float*)d_in[4];
    const float* bsa   = (const float*)d_in[5];
    const float* Wsa1  = (const float*)d_in[6];
    const float* Wsa2  = (const float*)d_in[7];
    const float* wsatw = (const float*)d_in[8];
    const float* wsatb = (const float*)d_in[9];
    const float* bsa1  = (const float*)d_in[10];
    const float* pw1   = (const float*)d_in[11];
    const float* pb1   = (const float*)d_in[12];
    const float* pw2   = (const float*)d_in[13];
    const float* pb2   = (const float*)d_in[14];
    const float* lng   = (const float*)d_in[15];
    const float* lnb   = (const float*)d_in[16];
    float* out = (float*)d_out;

    kprep<<<1,128>>>(W1,W2,wt_w,bsa,Wsa1,Wsa2,wsatw,wsatb,bsa1,c);
    kdots<<<(BL*32)/256,256>>>(x);
    ksm<<<BB,256>>>();
    kZ<<<dim3(32,4,BB),128>>>();
    kZfin<<<BL/256,256>>>();
    kS<<<dim3(32,4,BB),128>>>();
    kSfin<<<BL/256,256>>>();

    cudaFuncSetAttribute(kffn, cudaFuncAttributeMaxDynamicSharedMemorySize, 196608);
    kffn<<<BL/64,256,196608>>>(x,pw1,pb1,pw2,pb2,lng,lnb,out);
}

// round 2
// speedup vs baseline: 1.1750x; 1.1750x over previous
#include <cuda_runtime.h>

typedef unsigned long long ull;

#define BB 8
#define LL 4096
#define DX 128
#define BL (BB*LL)

// ---------------- scratch ----------------
__device__ float g_v1[DX], g_u1[DX], g_u2[DX];
__device__ float g_cq[BB];
__device__ float g_cconst;
__device__ float g_logits[BL], g_d1[BL], g_d2[BL];
__device__ float g_si[BL], g_sjc[BL];
__device__ float g_invZ[BL], g_S[BL];
__device__ float g_Zpart[BL*4], g_Spart[BL*4];
__device__ unsigned g_msi, g_msjc;   // max|si|, max|sjc| as uint bits

// ---------------- f32x2 helpers ----------------
__device__ __forceinline__ ull pk2(float x, float y){
    ull r; asm("mov.b64 %0,{%1,%2};" : "=l"(r) : "f"(x), "f"(y)); return r;
}
__device__ __forceinline__ ull fma2(ull a, ull b, ull c){
    ull d; asm("fma.rn.f32x2 %0,%1,%2,%3;" : "=l"(d) : "l"(a), "l"(b), "l"(c)); return d;
}
__device__ __forceinline__ ull add2(ull a, ull b){
    ull d; asm("add.rn.f32x2 %0,%1,%2;" : "=l"(d) : "l"(a), "l"(b)); return d;
}
__device__ __forceinline__ float2 upk2(ull p){
    float2 v; asm("mov.b64 {%0,%1},%2;" : "=f"(v.x), "=f"(v.y) : "l"(p)); return v;
}

// ---------------- exp(sigmoid(t)) : MUFU path ----------------
__device__ __forceinline__ float ex2a(float x){ float r; asm("ex2.approx.ftz.f32 %0,%1;":"=f"(r):"f"(x)); return r; }
__device__ __forceinline__ float rcpa(float x){ float r; asm("rcp.approx.ftz.f32 %0,%1;":"=f"(r):"f"(x)); return r; }
__device__ __forceinline__ float fsig(float t){
    const float L2E = 1.44269504088896f;
    float e = ex2a(t * -L2E);
    float s = rcpa(1.0f + e);
    return ex2a(s * L2E);
}

// ---------------- exp(sigmoid(t)) : Taylor deg-9, valid |t|<=1 (abs err <2e-5) ----------------
#define P0f  1.64872127f
#define P1f  0.412180318f
#define P2f  0.0515225397f
#define P3f (-0.03005490f)
#define P4f (-0.00831874f)
#define P5f  0.00237489f
#define P6f  0.00112763f
#define P7f (-1.56355e-4f)
#define P8f (-1.38606e-4f)
#define P9f  5.4551e-6f

__device__ __forceinline__ float fpoly(float t){
    float r = P9f;
    r = fmaf(r,t,P8f); r = fmaf(r,t,P7f); r = fmaf(r,t,P6f);
    r = fmaf(r,t,P5f); r = fmaf(r,t,P4f); r = fmaf(r,t,P3f);
    r = fmaf(r,t,P2f); r = fmaf(r,t,P1f); r = fmaf(r,t,P0f);
    return r;
}

#define HORNER2(r,t) do{ \
    r = fma2(c9,(t),c8); r = fma2(r,(t),c7); r = fma2(r,(t),c6); \
    r = fma2(r,(t),c5);  r = fma2(r,(t),c4); r = fma2(r,(t),c3); \
    r = fma2(r,(t),c2);  r = fma2(r,(t),c1); r = fma2(r,(t),c0); }while(0)

#define DECL_C2 \
    ull c0=pk2(P0f,P0f), c1=pk2(P1f,P1f), c2=pk2(P2f,P2f), c3=pk2(P3f,P3f), \
        c4=pk2(P4f,P4f), c5=pk2(P5f,P5f), c6=pk2(P6f,P6f), c7=pk2(P7f,P7f), \
        c8=pk2(P8f,P8f), c9=pk2(P9f,P9f)

__device__ __forceinline__ bool poly_ok(){
    return (__uint_as_float(g_msi) + __uint_as_float(g_msjc)) <= 1.0f;
}

// ---------------- kernel A: fold linear heads into vectors ----------------
__global__ void kprep(const float* __restrict__ W1, const float* __restrict__ W2,
                      const float* __restrict__ wt_w, const float* __restrict__ bsa,
                      const float* __restrict__ Wsa1, const float* __restrict__ Wsa2,
                      const float* __restrict__ wsat_w, const float* __restrict__ wsat_b,
                      const float* __restrict__ bsa1, const float* __restrict__ c)
{
    __shared__ float s_wt[DX], s_ws[DX], s_v2[DX], s_red[DX];
    int d = threadIdx.x;
    if (d == 0){ g_msi = 0u; g_msjc = 0u; }
    s_wt[d] = wt_w[d];
    s_ws[d] = wsat_w[d];
    __syncthreads();
    float v1=0.f, v2=0.f, u1=0.f, u2=0.f;
    #pragma unroll 4
    for (int e=0; e<DX; e++){
        v1 = fmaf(W1  [d*DX+e], s_wt[e], v1);
        v2 = fmaf(W2  [d*DX+e], s_wt[e], v2);
        u1 = fmaf(Wsa1[d*DX+e], s_ws[e], u1);
        u2 = fmaf(Wsa2[d*DX+e], s_ws[e], u2);
    }
    g_v1[d]=v1; g_u1[d]=u1; g_u2[d]=u2; s_v2[d]=v2;
    s_red[d] = bsa[d]*s_wt[d];
    __syncthreads();
    for (int o=64;o;o>>=1){ if(d<o) s_red[d]+=s_red[d+o]; __syncthreads(); }
    float bterm = s_red[0];
    __syncthreads();
    s_red[d] = bsa1[d]*s_ws[d];
    __syncthreads();
    for (int o=64;o;o>>=1){ if(d<o) s_red[d]+=s_red[d+o]; __syncthreads(); }
    if (d==0) g_cconst = s_red[0] + wsat_b[0];
    if (d < BB){
        float acc = bterm;
        for (int e=0;e<DX;e++) acc = fmaf(c[d*DX+e], s_v2[e], acc);
        g_cq[d] = acc;
    }
}

// ---------------- kernel B: per-row dots ----------------
__global__ void kdots(const float* __restrict__ x)
{
    int gt  = blockIdx.x*blockDim.x + threadIdx.x;
    int row = gt >> 5;
    int lane = gt & 31;
    if (row >= BL) return;
    float4 xv = ((const float4*)x)[row*32 + lane];
    float4 av = ((const float4*)g_v1)[lane];
    float4 bv = ((const float4*)g_u1)[lane];
    float4 cv = ((const float4*)g_u2)[lane];
    float s0 = xv.x*av.x + xv.y*av.y + xv.z*av.z + xv.w*av.w;
    float s1 = xv.x*bv.x + xv.y*bv.y + xv.z*bv.z + xv.w*bv.w;
    float s2 = xv.x*cv.x + xv.y*cv.y + xv.z*cv.z + xv.w*cv.w;
    #pragma unroll
    for (int o=16;o;o>>=1){
        s0 += __shfl_down_sync(0xffffffffu, s0, o);
        s1 += __shfl_down_sync(0xffffffffu, s1, o);
        s2 += __shfl_down_sync(0xffffffffu, s2, o);
    }
    if (lane==0){
        g_logits[row] = s0 + g_cq[row>>12];
        g_d1[row] = s1;
        g_d2[row] = s2;
    }
}

// ---------------- kernel C: softmax; emit si, sjc; track ranges ----------------
__global__ void ksm()
{
    int b = blockIdx.x, tid = threadIdx.x;
    __shared__ float red[256];
    const float* lg = g_logits + b*LL;
    float m = -1e30f;
    for (int i=tid;i<LL;i+=256) m = fmaxf(m, lg[i]);
    red[tid]=m; __syncthreads();
    for (int o=128;o;o>>=1){ if(tid<o) red[tid]=fmaxf(red[tid],red[tid+o]); __syncthreads(); }
    m = red[0]; __syncthreads();
    float s=0.f;
    for (int i=tid;i<LL;i+=256) s += __expf(lg[i]-m);
    red[tid]=s; __syncthreads();
    for (int o=128;o;o>>=1){ if(tid<o) red[tid]+=red[tid+o]; __syncthreads(); }
    float inv = 1.0f/red[0];
    float cc  = g_cconst;
    float lmsi = 0.f, lmsj = 0.f;
    for (int i=tid;i<LL;i+=256){
        float p = __expf(lg[i]-m)*inv;
        float si  = p*g_d1[b*LL+i];
        float sjc = fmaf(p, g_d2[b*LL+i], cc);
        g_si [b*LL+i] = si;
        g_sjc[b*LL+i] = sjc;
        lmsi = fmaxf(lmsi, fabsf(si));
        lmsj = fmaxf(lmsj, fabsf(sjc));
    }
    atomicMax(&g_msi,  __float_as_uint(lmsi));
    atomicMax(&g_msjc, __float_as_uint(lmsj));
}

// ---------------- kernel D: row sums Z ----------------
__global__ void __launch_bounds__(256) kZ()
{
    __shared__ __align__(16) float ssj[1024];
    int b = blockIdx.z, jt = blockIdx.y, it = blockIdx.x;
    const float* sjc = g_sjc + b*LL + jt*1024;
    for (int j=threadIdx.x;j<1024;j+=256) ssj[j]=sjc[j];
    __syncthreads();
    int i = it*256 + threadIdx.x;
    float si = g_si[b*LL+i];
    float res;
    if (poly_ok()){
        DECL_C2;
        ull si2 = pk2(si,si);
        ull a0=0ull, a1=0ull, a2=0ull, a3=0ull;
        const ull* pj = (const ull*)ssj;
        #pragma unroll 2
        for (int j=0;j<512;j+=4){
            ull t0=add2(si2,pj[j+0]), t1=add2(si2,pj[j+1]);
            ull t2=add2(si2,pj[j+2]), t3=add2(si2,pj[j+3]);
            ull r0,r1,r2,r3;
            HORNER2(r0,t0); HORNER2(r1,t1); HORNER2(r2,t2); HORNER2(r3,t3);
            a0=add2(a0,r0); a1=add2(a1,r1); a2=add2(a2,r2); a3=add2(a3,r3);
        }
        float2 v0=upk2(a0), v1=upk2(a1), v2=upk2(a2), v3=upk2(a3);
        res = ((v0.x+v0.y)+(v1.x+v1.y)) + ((v2.x+v2.y)+(v3.x+v3.y));
    } else {
        float a0=0.f,a1=0.f,a2=0.f,a3=0.f;
        #pragma unroll 2
        for (int j=0;j<1024;j+=4){
            a0 += fsig(si+ssj[j+0]);
            a1 += fsig(si+ssj[j+1]);
            a2 += fsig(si+ssj[j+2]);
            a3 += fsig(si+ssj[j+3]);
        }
        res = (a0+a1)+(a2+a3);
    }
    g_Zpart[(b*4+jt)*LL + i] = res;
}

__global__ void kZfin()
{
    int g = blockIdx.x*blockDim.x + threadIdx.x;
    int b = g >> 12, il = g & (LL-1);
    float Z = g_Zpart[(b*4+0)*LL+il] + g_Zpart[(b*4+1)*LL+il]
            + g_Zpart[(b*4+2)*LL+il] + g_Zpart[(b*4+3)*LL+il];
    float t = g_si[g] + g_sjc[g];
    Z -= poly_ok() ? fpoly(t) : fsig(t);
    g_invZ[g] = 1.0f / Z;
}

// ---------------- kernel E: column sums S ----------------
__global__ void __launch_bounds__(256) kS()
{
    __shared__ __align__(16) float ssi[1024];
    __shared__ __align__(16) float swz[1024];
    int b = blockIdx.z, ic = blockIdx.y, jt = blockIdx.x;
    int base = b*LL + ic*1024;
    for (int k=threadIdx.x;k<1024;k+=256){ ssi[k]=g_si[base+k]; swz[k]=g_invZ[base+k]; }
    __syncthreads();
    int j = jt*256 + threadIdx.x;
    float sj = g_sjc[b*LL+j];
    float res;
    if (poly_ok()){
        DECL_C2;
        ull sj2 = pk2(sj,sj);
        ull a0=0ull, a1=0ull, a2=0ull, a3=0ull;
        const ull* pi = (const ull*)ssi;
        const ull* pw = (const ull*)swz;
        #pragma unroll 2
        for (int i=0;i<512;i+=4){
            ull t0=add2(sj2,pi[i+0]), t1=add2(sj2,pi[i+1]);
            ull t2=add2(sj2,pi[i+2]), t3=add2(sj2,pi[i+3]);
            ull r0,r1,r2,r3;
            HORNER2(r0,t0); HORNER2(r1,t1); HORNER2(r2,t2); HORNER2(r3,t3);
            a0=fma2(r0,pw[i+0],a0); a1=fma2(r1,pw[i+1],a1);
            a2=fma2(r2,pw[i+2],a2); a3=fma2(r3,pw[i+3],a3);
        }
        float2 v0=upk2(a0), v1=upk2(a1), v2=upk2(a2), v3=upk2(a3);
        res = ((v0.x+v0.y)+(v1.x+v1.y)) + ((v2.x+v2.y)+(v3.x+v3.y));
    } else {
        float a0=0.f,a1=0.f,a2=0.f,a3=0.f;
        #pragma unroll 2
        for (int i=0;i<1024;i+=4){
            a0 = fmaf(fsig(sj+ssi[i+0]), swz[i+0], a0);
            a1 = fmaf(fsig(sj+ssi[i+1]), swz[i+1], a1);
            a2 = fmaf(fsig(sj+ssi[i+2]), swz[i+2], a2);
            a3 = fmaf(fsig(sj+ssi[i+3]), swz[i+3], a3);
        }
        res = (a0+a1)+(a2+a3);
    }
    g_Spart[(b*4+ic)*LL + j] = res;
}

__global__ void kSfin()
{
    int g = blockIdx.x*blockDim.x + threadIdx.x;
    int b = g >> 12, il = g & (LL-1);
    float S = g_Spart[(b*4+0)*LL+il] + g_Spart[(b*4+1)*LL+il]
            + g_Spart[(b*4+2)*LL+il] + g_Spart[(b*4+3)*LL+il];
    float t = g_si[g] + g_sjc[g];
    float f = poly_ok() ? fpoly(t) : fsig(t);
    S -= f * g_invZ[g];
    g_S[g] = S;
}

// ---------------- kernel F: fused ui -> FFN -> residual -> LayerNorm ----------------
// 128 rows/block, 256 threads (16 colgroups x 16 rowgroups), 8x8 tile/thread,
// f32x2-packed FMAs, staged weights (w1 then w2 in same 64KB smem buffer).
__device__ __forceinline__ void gemm2x(const float* __restrict__ ws,
                                       const float* __restrict__ in_s,
                                       int r0, int col, ull acc[8][4])
{
    #pragma unroll 2
    for (int d=0; d<DX; d+=4){
        ull w[4][4];
        #pragma unroll
        for (int dd=0; dd<4; dd++){
            float4 wa = *(const float4*)(ws + (d+dd)*DX + col);
            float4 wb = *(const float4*)(ws + (d+dd)*DX + col + 4);
            w[dd][0]=pk2(wa.x,wa.y); w[dd][1]=pk2(wa.z,wa.w);
            w[dd][2]=pk2(wb.x,wb.y); w[dd][3]=pk2(wb.z,wb.w);
        }
        #pragma unroll
        for (int r=0; r<8; r++){
            float4 xv = *(const float4*)(in_s + (r0+r)*DX + d);
            ull x0=pk2(xv.x,xv.x), x1=pk2(xv.y,xv.y);
            ull x2=pk2(xv.z,xv.z), x3=pk2(xv.w,xv.w);
            #pragma unroll
            for (int q=0; q<4; q++){
                acc[r][q] = fma2(x0, w[0][q], acc[r][q]);
                acc[r][q] = fma2(x1, w[1][q], acc[r][q]);
                acc[r][q] = fma2(x2, w[2][q], acc[r][q]);
                acc[r][q] = fma2(x3, w[3][q], acc[r][q]);
            }
        }
    }
}

__global__ void __launch_bounds__(256) kffn(const float* __restrict__ x,
        const float* __restrict__ w1, const float* __restrict__ b1,
        const float* __restrict__ w2, const float* __restrict__ b2,
        const float* __restrict__ lng, const float* __restrict__ lnb,
        float* __restrict__ out)
{
    extern __shared__ float sm[];
    float* ws  = sm;            // 16384 floats (current stage weights)
    float* ins = sm + 16384;    // 16384 floats (128 rows x 128)
    float* hs  = sm + 32768;    // 16384 floats

    int tid = threadIdx.x;
    int colg = tid & 15, rowg = tid >> 4;
    int col = colg*8, r0 = rowg*8;
    int rowbase = blockIdx.x * 128;

    // load ui = x*S into ins; load w1 into ws
    const float4* xr = (const float4*)(x + (size_t)rowbase*DX);
    for (int k=tid; k<4096; k+=256){
        float s = g_S[rowbase + (k>>5)];
        float4 v = xr[k];
        v.x*=s; v.y*=s; v.z*=s; v.w*=s;
        ((float4*)ins)[k] = v;
        ((float4*)ws)[k]  = ((const float4*)w1)[k];
    }
    __syncthreads();

    ull acc[8][4];

    // ---- stage 1: hidden = relu(ui @ W1 + b1) ----
    #pragma unroll
    for (int r=0;r<8;r++){ acc[r][0]=0ull; acc[r][1]=0ull; acc[r][2]=0ull; acc[r][3]=0ull; }
    gemm2x(ws, ins, r0, col, acc);
    {
        float4 bb0 = *(const float4*)(b1+col);
        float4 bb1 = *(const float4*)(b1+col+4);
        #pragma unroll
        for (int r=0;r<8;r++){
            float2 u0=upk2(acc[r][0]), u1=upk2(acc[r][1]);
            float2 u2=upk2(acc[r][2]), u3=upk2(acc[r][3]);
            float4 h0, h1;
            h0.x = fmaxf(u0.x+bb0.x, 0.f); h0.y = fmaxf(u0.y+bb0.y, 0.f);
            h0.z = fmaxf(u1.x+bb0.z, 0.f); h0.w = fmaxf(u1.y+bb0.w, 0.f);
            h1.x = fmaxf(u2.x+bb1.x, 0.f); h1.y = fmaxf(u2.y+bb1.y, 0.f);
            h1.z = fmaxf(u3.x+bb1.z, 0.f); h1.w = fmaxf(u3.y+bb1.w, 0.f);
            *(float4*)(hs + (r0+r)*DX + col)     = h0;
            *(float4*)(hs + (r0+r)*DX + col + 4) = h1;
        }
    }
    __syncthreads();

    // stage weights: overwrite ws with w2
    for (int k=tid; k<4096; k+=256)
        ((float4*)ws)[k] = ((const float4*)w2)[k];
    __syncthreads();

    // ---- stage 2: y = hidden @ W2 + b2 + ui; LayerNorm; store ----
    #pragma unroll
    for (int r=0;r<8;r++){ acc[r][0]=0ull; acc[r][1]=0ull; acc[r][2]=0ull; acc[r][3]=0ull; }
    gemm2x(ws, hs, r0, col, acc);
    {
        float4 bb0 = *(const float4*)(b2+col);
        float4 bb1 = *(const float4*)(b2+col+4);
        float4 g0  = *(const float4*)(lng+col);
        float4 g1  = *(const float4*)(lng+col+4);
        float4 be0 = *(const float4*)(lnb+col);
        float4 be1 = *(const float4*)(lnb+col+4);
        #pragma unroll
        for (int r=0;r<8;r++){
            float2 u0=upk2(acc[r][0]), u1=upk2(acc[r][1]);
            float2 u2=upk2(acc[r][2]), u3=upk2(acc[r][3]);
            float4 rs0 = *(const float4*)(ins + (r0+r)*DX + col);
            float4 rs1 = *(const float4*)(ins + (r0+r)*DX + col + 4);
            float y0 = u0.x+bb0.x+rs0.x, y1 = u0.y+bb0.y+rs0.y;
            float y2 = u1.x+bb0.z+rs0.z, y3 = u1.y+bb0.w+rs0.w;
            float y4 = u2.x+bb1.x+rs1.x, y5 = u2.y+bb1.y+rs1.y;
            float y6 = u3.x+bb1.z+rs1.z, y7 = u3.y+bb1.w+rs1.w;
            float s = ((y0+y1)+(y2+y3)) + ((y4+y5)+(y6+y7));
            #pragma unroll
            for (int o=1;o<16;o<<=1) s += __shfl_xor_sync(0xffffffffu, s, o);
            float mu = s * (1.0f/128.0f);
            float d0=y0-mu,d1=y1-mu,d2=y2-mu,d3=y3-mu;
            float d4=y4-mu,d5=y5-mu,d6=y6-mu,d7=y7-mu;
            float q = ((d0*d0+d1*d1)+(d2*d2+d3*d3)) + ((d4*d4+d5*d5)+(d6*d6+d7*d7));
            #pragma unroll
            for (int o=1;o<16;o<<=1) q += __shfl_xor_sync(0xffffffffu, q, o);
            float inv = rsqrtf(q*(1.0f/128.0f) + 1e-6f);
            float4 o0, o1;
            o0.x = d0*inv*g0.x + be0.x; o0.y = d1*inv*g0.y + be0.y;
            o0.z = d2*inv*g0.z + be0.z; o0.w = d3*inv*g0.w + be0.w;
            o1.x = d4*inv*g1.x + be1.x; o1.y = d5*inv*g1.y + be1.y;
            o1.z = d6*inv*g1.z + be1.z; o1.w = d7*inv*g1.w + be1.w;
            float* orow = out + (size_t)(rowbase + r0 + r)*DX;
            *(float4*)(orow + col)     = o0;
            *(float4*)(orow + col + 4) = o1;
        }
    }
}

// ---------------- launch ----------------
extern "C" void kernel_launch(void* const* d_in, const int* in_sizes, int n_in,
                              void* d_out, int out_size)
{
    const float* x     = (const float*)d_in[0];
    const float* c     = (const float*)d_in[1];
    const float* W1    = (const float*)d_in[2];
    const float* W2    = (const float*)d_in[3];
    const float* wt_w  = (const float*)d_in[4];
    const float* bsa   = (const float*)d_in[5];
    const float* Wsa1  = (const float*)d_in[6];
    const float* Wsa2  = (const float*)d_in[7];
    const float* wsatw = (const float*)d_in[8];
    const float* wsatb = (const float*)d_in[9];
    const float* bsa1  = (const float*)d_in[10];
    const float* pw1   = (const float*)d_in[11];
    const float* pb1   = (const float*)d_in[12];
    const float* pw2   = (const float*)d_in[13];
    const float* pb2   = (const float*)d_in[14];
    const float* lng   = (const float*)d_in[15];
    const float* lnb   = (const float*)d_in[16];
    float* out = (float*)d_out;

    kprep<<<1,128>>>(W1,W2,wt_w,bsa,Wsa1,Wsa2,wsatw,wsatb,bsa1,c);
    kdots<<<(BL*32)/256,256>>>(x);
    ksm<<<BB,256>>>();
    kZ<<<dim3(16,4,BB),256>>>();
    kZfin<<<BL/256,256>>>();
    kS<<<dim3(16,4,BB),256>>>();
    kSfin<<<BL/256,256>>>();

    cudaFuncSetAttribute(kffn, cudaFuncAttributeMaxDynamicSharedMemorySize, 196608);
    kffn<<<BL/128,256,196608>>>(x,pw1,pb1,pw2,pb2,lng,lnb,out);
}

// round 3
// speedup vs baseline: 1.7487x; 1.4883x over previous
#include <cuda_runtime.h>

typedef unsigned long long ull;

#define BB 8
#define LL 4096
#define DX 128
#define BL (BB*LL)

// ---------------- scratch ----------------
__device__ float g_v1[DX], g_u1[DX], g_u2[DX];
__device__ float g_cq[BB];
__device__ float g_cconst;
__device__ float g_logits[BL], g_d1[BL], g_d2[BL];
__device__ float g_si[BL], g_sjc[BL];
__device__ float g_invZ[BL], g_S[BL];
__device__ float g_Zpart[BL*4], g_Spart[BL*4];
__device__ float g_E[BB][10], g_F[BB][10];
__device__ unsigned g_msi, g_msjc;   // max|si|, max|sjc| as uint bits

// ---------------- exp(sigmoid(t)) Taylor deg-9, valid |t|<=1 ----------------
#define P0f  1.64872127f
#define P1f  0.412180318f
#define P2f  0.0515225397f
#define P3f (-0.03005490f)
#define P4f (-0.00831874f)
#define P5f  0.00237489f
#define P6f  0.00112763f
#define P7f (-1.56355e-4f)
#define P8f (-1.38606e-4f)
#define P9f  5.4551e-6f

__constant__ float c_P[10] = {P0f,P1f,P2f,P3f,P4f,P5f,P6f,P7f,P8f,P9f};
__constant__ float c_BIN[10][10] = {
    {1,0,0,0,0,0,0,0,0,0},
    {1,1,0,0,0,0,0,0,0,0},
    {1,2,1,0,0,0,0,0,0,0},
    {1,3,3,1,0,0,0,0,0,0},
    {1,4,6,4,1,0,0,0,0,0},
    {1,5,10,10,5,1,0,0,0,0},
    {1,6,15,20,15,6,1,0,0,0},
    {1,7,21,35,35,21,7,1,0,0},
    {1,8,28,56,70,56,28,8,1,0},
    {1,9,36,84,126,126,84,36,9,1},
};

__device__ __forceinline__ float fpoly(float t){
    float r = P9f;
    r = fmaf(r,t,P8f); r = fmaf(r,t,P7f); r = fmaf(r,t,P6f);
    r = fmaf(r,t,P5f); r = fmaf(r,t,P4f); r = fmaf(r,t,P3f);
    r = fmaf(r,t,P2f); r = fmaf(r,t,P1f); r = fmaf(r,t,P0f);
    return r;
}

// MUFU fallback f
__device__ __forceinline__ float ex2a(float x){ float r; asm("ex2.approx.ftz.f32 %0,%1;":"=f"(r):"f"(x)); return r; }
__device__ __forceinline__ float rcpa(float x){ float r; asm("rcp.approx.ftz.f32 %0,%1;":"=f"(r):"f"(x)); return r; }
__device__ __forceinline__ float fsig(float t){
    const float L2E = 1.44269504088896f;
    float e = ex2a(t * -L2E);
    float s = rcpa(1.0f + e);
    return ex2a(s * L2E);
}

__device__ __forceinline__ bool poly_ok(){
    return (__uint_as_float(g_msi) + __uint_as_float(g_msjc)) <= 1.0f;
}

// ---------------- f32x2 helpers (ffn + fallback) ----------------
__device__ __forceinline__ ull pk2(float x, float y){
    ull r; asm("mov.b64 %0,{%1,%2};" : "=l"(r) : "f"(x), "f"(y)); return r;
}
__device__ __forceinline__ ull fma2(ull a, ull b, ull c){
    ull d; asm("fma.rn.f32x2 %0,%1,%2,%3;" : "=l"(d) : "l"(a), "l"(b), "l"(c)); return d;
}
__device__ __forceinline__ ull add2(ull a, ull b){
    ull d; asm("add.rn.f32x2 %0,%1,%2;" : "=l"(d) : "l"(a), "l"(b)); return d;
}
__device__ __forceinline__ float2 upk2(ull p){
    float2 v; asm("mov.b64 {%0,%1},%2;" : "=f"(v.x), "=f"(v.y) : "l"(p)); return v;
}

#define HORNER2(r,t) do{ \
    r = fma2(c9,(t),c8); r = fma2(r,(t),c7); r = fma2(r,(t),c6); \
    r = fma2(r,(t),c5);  r = fma2(r,(t),c4); r = fma2(r,(t),c3); \
    r = fma2(r,(t),c2);  r = fma2(r,(t),c1); r = fma2(r,(t),c0); }while(0)

#define DECL_C2 \
    ull c0=pk2(P0f,P0f), c1=pk2(P1f,P1f), c2=pk2(P2f,P2f), c3=pk2(P3f,P3f), \
        c4=pk2(P4f,P4f), c5=pk2(P5f,P5f), c6=pk2(P6f,P6f), c7=pk2(P7f,P7f), \
        c8=pk2(P8f,P8f), c9=pk2(P9f,P9f)

// ---------------- kernel A: fold linear heads ----------------
__global__ void kprep(const float* __restrict__ W1, const float* __restrict__ W2,
                      const float* __restrict__ wt_w, const float* __restrict__ bsa,
                      const float* __restrict__ Wsa1, const float* __restrict__ Wsa2,
                      const float* __restrict__ wsat_w, const float* __restrict__ wsat_b,
                      const float* __restrict__ bsa1, const float* __restrict__ c)
{
    __shared__ float s_wt[DX], s_ws[DX], s_v2[DX], s_red[DX];
    int d = threadIdx.x;
    if (d == 0){ g_msi = 0u; g_msjc = 0u; }
    s_wt[d] = wt_w[d];
    s_ws[d] = wsat_w[d];
    __syncthreads();
    float v1=0.f, v2=0.f, u1=0.f, u2=0.f;
    #pragma unroll 4
    for (int e=0; e<DX; e++){
        v1 = fmaf(W1  [d*DX+e], s_wt[e], v1);
        v2 = fmaf(W2  [d*DX+e], s_wt[e], v2);
        u1 = fmaf(Wsa1[d*DX+e], s_ws[e], u1);
        u2 = fmaf(Wsa2[d*DX+e], s_ws[e], u2);
    }
    g_v1[d]=v1; g_u1[d]=u1; g_u2[d]=u2; s_v2[d]=v2;
    s_red[d] = bsa[d]*s_wt[d];
    __syncthreads();
    for (int o=64;o;o>>=1){ if(d<o) s_red[d]+=s_red[d+o]; __syncthreads(); }
    float bterm = s_red[0];
    __syncthreads();
    s_red[d] = bsa1[d]*s_ws[d];
    __syncthreads();
    for (int o=64;o;o>>=1){ if(d<o) s_red[d]+=s_red[d+o]; __syncthreads(); }
    if (d==0) g_cconst = s_red[0] + wsat_b[0];
    if (d < BB){
        float acc = bterm;
        for (int e=0;e<DX;e++) acc = fmaf(c[d*DX+e], s_v2[e], acc);
        g_cq[d] = acc;
    }
}

// ---------------- kernel B: per-row dots ----------------
__global__ void kdots(const float* __restrict__ x)
{
    int gt  = blockIdx.x*blockDim.x + threadIdx.x;
    int row = gt >> 5;
    int lane = gt & 31;
    if (row >= BL) return;
    float4 xv = ((const float4*)x)[row*32 + lane];
    float4 av = ((const float4*)g_v1)[lane];
    float4 bv = ((const float4*)g_u1)[lane];
    float4 cv = ((const float4*)g_u2)[lane];
    float s0 = xv.x*av.x + xv.y*av.y + xv.z*av.z + xv.w*av.w;
    float s1 = xv.x*bv.x + xv.y*bv.y + xv.z*bv.z + xv.w*bv.w;
    float s2 = xv.x*cv.x + xv.y*cv.y + xv.z*cv.z + xv.w*cv.w;
    #pragma unroll
    for (int o=16;o;o>>=1){
        s0 += __shfl_down_sync(0xffffffffu, s0, o);
        s1 += __shfl_down_sync(0xffffffffu, s1, o);
        s2 += __shfl_down_sync(0xffffffffu, s2, o);
    }
    if (lane==0){
        g_logits[row] = s0 + g_cq[row>>12];
        g_d1[row] = s1;
        g_d2[row] = s2;
    }
}

// ---------------- kernel C: softmax; emit si, sjc; track ranges ----------------
__global__ void ksm()
{
    int b = blockIdx.x, tid = threadIdx.x;
    __shared__ float red[256];
    const float* lg = g_logits + b*LL;
    float m = -1e30f;
    for (int i=tid;i<LL;i+=256) m = fmaxf(m, lg[i]);
    red[tid]=m; __syncthreads();
    for (int o=128;o;o>>=1){ if(tid<o) red[tid]=fmaxf(red[tid],red[tid+o]); __syncthreads(); }
    m = red[0]; __syncthreads();
    float s=0.f;
    for (int i=tid;i<LL;i+=256) s += __expf(lg[i]-m);
    red[tid]=s; __syncthreads();
    for (int o=128;o;o>>=1){ if(tid<o) red[tid]+=red[tid+o]; __syncthreads(); }
    float inv = 1.0f/red[0];
    float cc  = g_cconst;
    float lmsi = 0.f, lmsj = 0.f;
    for (int i=tid;i<LL;i+=256){
        float p = __expf(lg[i]-m)*inv;
        float si  = p*g_d1[b*LL+i];
        float sjc = fmaf(p, g_d2[b*LL+i], cc);
        g_si [b*LL+i] = si;
        g_sjc[b*LL+i] = sjc;
        lmsi = fmaxf(lmsi, fabsf(si));
        lmsj = fmaxf(lmsj, fabsf(sjc));
    }
    atomicMax(&g_msi,  __float_as_uint(lmsi));
    atomicMax(&g_msjc, __float_as_uint(lmsj));
}

// ============ POLY FAST PATH: moments -> rank-10 row/col sums ============

// moments of sjc per batch -> E_k
__global__ void kmomE()
{
    if (!poly_ok()) return;
    int b = blockIdx.x, tid = threadIdx.x;
    float m[10];
    #pragma unroll
    for (int k=0;k<10;k++) m[k]=0.f;
    const float* sjc = g_sjc + b*LL;
    for (int j=tid;j<LL;j+=256){
        float t = sjc[j], p = 1.f;
        #pragma unroll
        for (int k=0;k<10;k++){ m[k]+=p; p*=t; }
    }
    __shared__ float red[256];
    __shared__ float M[10];
    for (int k=0;k<10;k++){
        red[tid]=m[k]; __syncthreads();
        for (int o=128;o;o>>=1){ if(tid<o) red[tid]+=red[tid+o]; __syncthreads(); }
        if (tid==0) M[k]=red[0];
        __syncthreads();
    }
    if (tid < 10){
        float e = 0.f;
        for (int mm=0; tid+mm<10; mm++)
            e = fmaf(c_P[tid+mm]*c_BIN[tid+mm][tid], M[mm], e);
        g_E[b][tid] = e;
    }
}

// per-row Z_i = Horner(si, E) - fpoly(si+sjc); invZ = 1/Z
__global__ void kZpoly()
{
    if (!poly_ok()) return;
    int g = blockIdx.x*blockDim.x + threadIdx.x;
    int b = g >> 12;
    float si = g_si[g];
    const float* E = g_E[b];
    float z = E[9];
    #pragma unroll
    for (int k=8;k>=0;k--) z = fmaf(z, si, E[k]);
    z -= fpoly(si + g_sjc[g]);
    g_invZ[g] = 1.0f / z;
}

// invZ-weighted moments of si per batch -> F_k
__global__ void kmomF()
{
    if (!poly_ok()) return;
    int b = blockIdx.x, tid = threadIdx.x;
    float m[10];
    #pragma unroll
    for (int k=0;k<10;k++) m[k]=0.f;
    const float* si = g_si + b*LL;
    const float* wz = g_invZ + b*LL;
    for (int i=tid;i<LL;i+=256){
        float t = si[i], w = wz[i], p = w;
        #pragma unroll
        for (int k=0;k<10;k++){ m[k]+=p; p*=t; }
    }
    __shared__ float red[256];
    __shared__ float M[10];
    for (int k=0;k<10;k++){
        red[tid]=m[k]; __syncthreads();
        for (int o=128;o;o>>=1){ if(tid<o) red[tid]+=red[tid+o]; __syncthreads(); }
        if (tid==0) M[k]=red[0];
        __syncthreads();
    }
    if (tid < 10){
        float e = 0.f;
        for (int mm=0; tid+mm<10; mm++)
            e = fmaf(c_P[tid+mm]*c_BIN[tid+mm][tid], M[mm], e);
        g_F[b][tid] = e;
    }
}

// per-col S_j = Horner(sjc, F) - invZ_j*fpoly(si+sjc)
__global__ void kSpoly()
{
    if (!poly_ok()) return;
    int g = blockIdx.x*blockDim.x + threadIdx.x;
    int b = g >> 12;
    float sj = g_sjc[g];
    const float* F = g_F[b];
    float s = F[9];
    #pragma unroll
    for (int k=8;k>=0;k--) s = fmaf(s, sj, F[k]);
    s -= fpoly(g_si[g] + sj) * g_invZ[g];
    g_S[g] = s;
}

// ============ MUFU FALLBACK PATH (gated: runs only if range > 1) ============

__global__ void __launch_bounds__(256) kZfb()
{
    if (poly_ok()) return;
    __shared__ __align__(16) float ssj[1024];
    int b = blockIdx.z, jt = blockIdx.y, it = blockIdx.x;
    const float* sjc = g_sjc + b*LL + jt*1024;
    for (int j=threadIdx.x;j<1024;j+=256) ssj[j]=sjc[j];
    __syncthreads();
    int i = it*256 + threadIdx.x;
    float si = g_si[b*LL+i];
    float a0=0.f,a1=0.f,a2=0.f,a3=0.f;
    #pragma unroll 2
    for (int j=0;j<1024;j+=4){
        a0 += fsig(si+ssj[j+0]);
        a1 += fsig(si+ssj[j+1]);
        a2 += fsig(si+ssj[j+2]);
        a3 += fsig(si+ssj[j+3]);
    }
    g_Zpart[(b*4+jt)*LL + i] = (a0+a1)+(a2+a3);
}

__global__ void kZfbfin()
{
    if (poly_ok()) return;
    int g = blockIdx.x*blockDim.x + threadIdx.x;
    int b = g >> 12, il = g & (LL-1);
    float Z = g_Zpart[(b*4+0)*LL+il] + g_Zpart[(b*4+1)*LL+il]
            + g_Zpart[(b*4+2)*LL+il] + g_Zpart[(b*4+3)*LL+il];
    Z -= fsig(g_si[g] + g_sjc[g]);
    g_invZ[g] = 1.0f / Z;
}

__global__ void __launch_bounds__(256) kSfb()
{
    if (poly_ok()) return;
    __shared__ __align__(16) float ssi[1024];
    __shared__ __align__(16) float swz[1024];
    int b = blockIdx.z, ic = blockIdx.y, jt = blockIdx.x;
    int base = b*LL + ic*1024;
    for (int k=threadIdx.x;k<1024;k+=256){ ssi[k]=g_si[base+k]; swz[k]=g_invZ[base+k]; }
    __syncthreads();
    int j = jt*256 + threadIdx.x;
    float sj = g_sjc[b*LL+j];
    float a0=0.f,a1=0.f,a2=0.f,a3=0.f;
    #pragma unroll 2
    for (int i=0;i<1024;i+=4){
        a0 = fmaf(fsig(sj+ssi[i+0]), swz[i+0], a0);
        a1 = fmaf(fsig(sj+ssi[i+1]), swz[i+1], a1);
        a2 = fmaf(fsig(sj+ssi[i+2]), swz[i+2], a2);
        a3 = fmaf(fsig(sj+ssi[i+3]), swz[i+3], a3);
    }
    g_Spart[(b*4+ic)*LL + j] = (a0+a1)+(a2+a3);
}

__global__ void kSfbfin()
{
    if (poly_ok()) return;
    int g = blockIdx.x*blockDim.x + threadIdx.x;
    int b = g >> 12, il = g & (LL-1);
    float S = g_Spart[(b*4+0)*LL+il] + g_Spart[(b*4+1)*LL+il]
            + g_Spart[(b*4+2)*LL+il] + g_Spart[(b*4+3)*LL+il];
    S -= fsig(g_si[g] + g_sjc[g]) * g_invZ[g];
    g_S[g] = S;
}

// ---------------- kernel F: fused ui -> FFN -> residual -> LayerNorm ----------------
__device__ __forceinline__ void gemm2x(const float* __restrict__ ws,
                                       const float* __restrict__ in_s,
                                       int r0, int col, ull acc[8][4])
{
    #pragma unroll 2
    for (int d=0; d<DX; d+=4){
        ull w[4][4];
        #pragma unroll
        for (int dd=0; dd<4; dd++){
            float4 wa = *(const float4*)(ws + (d+dd)*DX + col);
            float4 wb = *(const float4*)(ws + (d+dd)*DX + col + 4);
            w[dd][0]=pk2(wa.x,wa.y); w[dd][1]=pk2(wa.z,wa.w);
            w[dd][2]=pk2(wb.x,wb.y); w[dd][3]=pk2(wb.z,wb.w);
        }
        #pragma unroll
        for (int r=0; r<8; r++){
            float4 xv = *(const float4*)(in_s + (r0+r)*DX + d);
            ull x0=pk2(xv.x,xv.x), x1=pk2(xv.y,xv.y);
            ull x2=pk2(xv.z,xv.z), x3=pk2(xv.w,xv.w);
            #pragma unroll
            for (int q=0; q<4; q++){
                acc[r][q] = fma2(x0, w[0][q], acc[r][q]);
                acc[r][q] = fma2(x1, w[1][q], acc[r][q]);
                acc[r][q] = fma2(x2, w[2][q], acc[r][q]);
                acc[r][q] = fma2(x3, w[3][q], acc[r][q]);
            }
        }
    }
}

__global__ void __launch_bounds__(256) kffn(const float* __restrict__ x,
        const float* __restrict__ w1, const float* __restrict__ b1,
        const float* __restrict__ w2, const float* __restrict__ b2,
        const float* __restrict__ lng, const float* __restrict__ lnb,
        float* __restrict__ out)
{
    extern __shared__ float sm[];
    float* ws  = sm;            // 16384 floats (current stage weights)
    float* ins = sm + 16384;    // 16384 floats (128 rows x 128)
    float* hs  = sm + 32768;    // 16384 floats

    int tid = threadIdx.x;
    int colg = tid & 15, rowg = tid >> 4;
    int col = colg*8, r0 = rowg*8;
    int rowbase = blockIdx.x * 128;

    const float4* xr = (const float4*)(x + (size_t)rowbase*DX);
    for (int k=tid; k<4096; k+=256){
        float s = g_S[rowbase + (k>>5)];
        float4 v = xr[k];
        v.x*=s; v.y*=s; v.z*=s; v.w*=s;
        ((float4*)ins)[k] = v;
        ((float4*)ws)[k]  = ((const float4*)w1)[k];
    }
    __syncthreads();

    ull acc[8][4];

    // ---- stage 1: hidden = relu(ui @ W1 + b1) ----
    #pragma unroll
    for (int r=0;r<8;r++){ acc[r][0]=0ull; acc[r][1]=0ull; acc[r][2]=0ull; acc[r][3]=0ull; }
    gemm2x(ws, ins, r0, col, acc);
    {
        float4 bb0 = *(const float4*)(b1+col);
        float4 bb1 = *(const float4*)(b1+col+4);
        #pragma unroll
        for (int r=0;r<8;r++){
            float2 u0=upk2(acc[r][0]), u1=upk2(acc[r][1]);
            float2 u2=upk2(acc[r][2]), u3=upk2(acc[r][3]);
            float4 h0, h1;
            h0.x = fmaxf(u0.x+bb0.x, 0.f); h0.y = fmaxf(u0.y+bb0.y, 0.f);
            h0.z = fmaxf(u1.x+bb0.z, 0.f); h0.w = fmaxf(u1.y+bb0.w, 0.f);
            h1.x = fmaxf(u2.x+bb1.x, 0.f); h1.y = fmaxf(u2.y+bb1.y, 0.f);
            h1.z = fmaxf(u3.x+bb1.z, 0.f); h1.w = fmaxf(u3.y+bb1.w, 0.f);
            *(float4*)(hs + (r0+r)*DX + col)     = h0;
            *(float4*)(hs + (r0+r)*DX + col + 4) = h1;
        }
    }
    __syncthreads();

    for (int k=tid; k<4096; k+=256)
        ((float4*)ws)[k] = ((const float4*)w2)[k];
    __syncthreads();

    // ---- stage 2: y = hidden @ W2 + b2 + ui; LayerNorm; store ----
    #pragma unroll
    for (int r=0;r<8;r++){ acc[r][0]=0ull; acc[r][1]=0ull; acc[r][2]=0ull; acc[r][3]=0ull; }
    gemm2x(ws, hs, r0, col, acc);
    {
        float4 bb0 = *(const float4*)(b2+col);
        float4 bb1 = *(const float4*)(b2+col+4);
        float4 g0  = *(const float4*)(lng+col);
        float4 g1  = *(const float4*)(lng+col+4);
        float4 be0 = *(const float4*)(lnb+col);
        float4 be1 = *(const float4*)(lnb+col+4);
        #pragma unroll
        for (int r=0;r<8;r++){
            float2 u0=upk2(acc[r][0]), u1=upk2(acc[r][1]);
            float2 u2=upk2(acc[r][2]), u3=upk2(acc[r][3]);
            float4 rs0 = *(const float4*)(ins + (r0+r)*DX + col);
            float4 rs1 = *(const float4*)(ins + (r0+r)*DX + col + 4);
            float y0 = u0.x+bb0.x+rs0.x, y1 = u0.y+bb0.y+rs0.y;
            float y2 = u1.x+bb0.z+rs0.z, y3 = u1.y+bb0.w+rs0.w;
            float y4 = u2.x+bb1.x+rs1.x, y5 = u2.y+bb1.y+rs1.y;
            float y6 = u3.x+bb1.z+rs1.z, y7 = u3.y+bb1.w+rs1.w;
            float s = ((y0+y1)+(y2+y3)) + ((y4+y5)+(y6+y7));
            #pragma unroll
            for (int o=1;o<16;o<<=1) s += __shfl_xor_sync(0xffffffffu, s, o);
            float mu = s * (1.0f/128.0f);
            float d0=y0-mu,d1=y1-mu,d2=y2-mu,d3=y3-mu;
            float d4=y4-mu,d5=y5-mu,d6=y6-mu,d7=y7-mu;
            float q = ((d0*d0+d1*d1)+(d2*d2+d3*d3)) + ((d4*d4+d5*d5)+(d6*d6+d7*d7));
            #pragma unroll
            for (int o=1;o<16;o<<=1) q += __shfl_xor_sync(0xffffffffu, q, o);
            float inv = rsqrtf(q*(1.0f/128.0f) + 1e-6f);
            float4 o0, o1;
            o0.x = d0*inv*g0.x + be0.x; o0.y = d1*inv*g0.y + be0.y;
            o0.z = d2*inv*g0.z + be0.z; o0.w = d3*inv*g0.w + be0.w;
            o1.x = d4*inv*g1.x + be1.x; o1.y = d5*inv*g1.y + be1.y;
            o1.z = d6*inv*g1.z + be1.z; o1.w = d7*inv*g1.w + be1.w;
            float* orow = out + (size_t)(rowbase + r0 + r)*DX;
            *(float4*)(orow + col)     = o0;
            *(float4*)(orow + col + 4) = o1;
        }
    }
}

// ---------------- launch ----------------
extern "C" void kernel_launch(void* const* d_in, const int* in_sizes, int n_in,
                              void* d_out, int out_size)
{
    const float* x     = (const float*)d_in[0];
    const float* c     = (const float*)d_in[1];
    const float* W1    = (const float*)d_in[2];
    const float* W2    = (const float*)d_in[3];
    const float* wt_w  = (const float*)d_in[4];
    const float* bsa   = (const float*)d_in[5];
    const float* Wsa1  = (const float*)d_in[6];
    const float* Wsa2  = (const float*)d_in[7];
    const float* wsatw = (const float*)d_in[8];
    const float* wsatb = (const float*)d_in[9];
    const float* bsa1  = (const float*)d_in[10];
    const float* pw1   = (const float*)d_in[11];
    const float* pb1   = (const float*)d_in[12];
    const float* pw2   = (const float*)d_in[13];
    const float* pb2   = (const float*)d_in[14];
    const float* lng   = (const float*)d_in[15];
    const float* lnb   = (const float*)d_in[16];
    float* out = (float*)d_out;

    kprep<<<1,128>>>(W1,W2,wt_w,bsa,Wsa1,Wsa2,wsatw,wsatb,bsa1,c);
    kdots<<<(BL*32)/256,256>>>(x);
    ksm<<<BB,256>>>();

    // poly fast path (O(L) via moments)
    kmomE<<<BB,256>>>();
    kZpoly<<<BL/256,256>>>();
    kmomF<<<BB,256>>>();
    kSpoly<<<BL/256,256>>>();

    // MUFU fallback (early-exits when poly path valid)
    kZfb<<<dim3(16,4,BB),256>>>();
    kZfbfin<<<BL/256,256>>>();
    kSfb<<<dim3(16,4,BB),256>>>();
    kSfbfin<<<BL/256,256>>>();

    cudaFuncSetAttribute(kffn, cudaFuncAttributeMaxDynamicSharedMemorySize, 196608);
    kffn<<<BL/128,256,196608>>>(x,pw1,pb1,pw2,pb2,lng,lnb,out);
}

// round 4
// speedup vs baseline: 1.9199x; 1.0979x over previous
#include <cuda_runtime.h>

typedef unsigned long long ull;

#define BB 8
#define LL 4096
#define DX 128
#define BL (BB*LL)

// ---------------- scratch ----------------
__device__ float g_v1[DX], g_u1[DX], g_u2[DX];
__device__ float g_cq[BB];
__device__ float g_cconst;
__device__ float g_logits[BL], g_d1[BL], g_d2[BL];
__device__ float g_si[BL], g_sjc[BL];
__device__ float g_invZ[BL], g_S[BL];
__device__ float g_Zpart[BL*4], g_Spart[BL*4];
__device__ float g_E[BB][10], g_F[BB][10];
__device__ unsigned g_msi, g_msjc;   // max|si|, max|sjc| as uint bits

// ---------------- exp(sigmoid(t)) Taylor deg-9, valid |t|<=1 ----------------
#define P0f  1.64872127f
#define P1f  0.412180318f
#define P2f  0.0515225397f
#define P3f (-0.03005490f)
#define P4f (-0.00831874f)
#define P5f  0.00237489f
#define P6f  0.00112763f
#define P7f (-1.56355e-4f)
#define P8f (-1.38606e-4f)
#define P9f  5.4551e-6f

__constant__ float c_P[10] = {P0f,P1f,P2f,P3f,P4f,P5f,P6f,P7f,P8f,P9f};
__constant__ float c_BIN[10][10] = {
    {1,0,0,0,0,0,0,0,0,0},
    {1,1,0,0,0,0,0,0,0,0},
    {1,2,1,0,0,0,0,0,0,0},
    {1,3,3,1,0,0,0,0,0,0},
    {1,4,6,4,1,0,0,0,0,0},
    {1,5,10,10,5,1,0,0,0,0},
    {1,6,15,20,15,6,1,0,0,0},
    {1,7,21,35,35,21,7,1,0,0},
    {1,8,28,56,70,56,28,8,1,0},
    {1,9,36,84,126,126,84,36,9,1},
};

__device__ __forceinline__ float fpoly(float t){
    float r = P9f;
    r = fmaf(r,t,P8f); r = fmaf(r,t,P7f); r = fmaf(r,t,P6f);
    r = fmaf(r,t,P5f); r = fmaf(r,t,P4f); r = fmaf(r,t,P3f);
    r = fmaf(r,t,P2f); r = fmaf(r,t,P1f); r = fmaf(r,t,P0f);
    return r;
}

// MUFU fallback f
__device__ __forceinline__ float ex2a(float x){ float r; asm("ex2.approx.ftz.f32 %0,%1;":"=f"(r):"f"(x)); return r; }
__device__ __forceinline__ float rcpa(float x){ float r; asm("rcp.approx.ftz.f32 %0,%1;":"=f"(r):"f"(x)); return r; }
__device__ __forceinline__ float fsig(float t){
    const float L2E = 1.44269504088896f;
    float e = ex2a(t * -L2E);
    float s = rcpa(1.0f + e);
    return ex2a(s * L2E);
}

__device__ __forceinline__ bool poly_ok(){
    return (__uint_as_float(g_msi) + __uint_as_float(g_msjc)) <= 1.0f;
}

// ---------------- f32x2 helpers ----------------
__device__ __forceinline__ ull pk2(float x, float y){
    ull r; asm("mov.b64 %0,{%1,%2};" : "=l"(r) : "f"(x), "f"(y)); return r;
}
__device__ __forceinline__ ull fma2(ull a, ull b, ull c){
    ull d; asm("fma.rn.f32x2 %0,%1,%2,%3;" : "=l"(d) : "l"(a), "l"(b), "l"(c)); return d;
}
__device__ __forceinline__ float2 upk2(ull p){
    float2 v; asm("mov.b64 {%0,%1},%2;" : "=f"(v.x), "=f"(v.y) : "l"(p)); return v;
}

// warp reduce add
__device__ __forceinline__ float wradd(float v){
    #pragma unroll
    for (int o=16;o;o>>=1) v += __shfl_xor_sync(0xffffffffu, v, o);
    return v;
}
__device__ __forceinline__ float wrmax(float v){
    #pragma unroll
    for (int o=16;o;o>>=1) v = fmaxf(v, __shfl_xor_sync(0xffffffffu, v, o));
    return v;
}

// ---------------- kernel A: fold linear heads ----------------
__global__ void kprep(const float* __restrict__ W1, const float* __restrict__ W2,
                      const float* __restrict__ wt_w, const float* __restrict__ bsa,
                      const float* __restrict__ Wsa1, const float* __restrict__ Wsa2,
                      const float* __restrict__ wsat_w, const float* __restrict__ wsat_b,
                      const float* __restrict__ bsa1, const float* __restrict__ c)
{
    __shared__ float s_wt[DX], s_ws[DX], s_v2[DX], s_red[DX];
    int d = threadIdx.x;
    if (d == 0){ g_msi = 0u; g_msjc = 0u; }
    s_wt[d] = wt_w[d];
    s_ws[d] = wsat_w[d];
    __syncthreads();
    float v1=0.f, v2=0.f, u1=0.f, u2=0.f;
    #pragma unroll 4
    for (int e=0; e<DX; e++){
        v1 = fmaf(W1  [d*DX+e], s_wt[e], v1);
        v2 = fmaf(W2  [d*DX+e], s_wt[e], v2);
        u1 = fmaf(Wsa1[d*DX+e], s_ws[e], u1);
        u2 = fmaf(Wsa2[d*DX+e], s_ws[e], u2);
    }
    g_v1[d]=v1; g_u1[d]=u1; g_u2[d]=u2; s_v2[d]=v2;
    s_red[d] = bsa[d]*s_wt[d];
    __syncthreads();
    for (int o=64;o;o>>=1){ if(d<o) s_red[d]+=s_red[d+o]; __syncthreads(); }
    float bterm = s_red[0];
    __syncthreads();
    s_red[d] = bsa1[d]*s_ws[d];
    __syncthreads();
    for (int o=64;o;o>>=1){ if(d<o) s_red[d]+=s_red[d+o]; __syncthreads(); }
    if (d==0) g_cconst = s_red[0] + wsat_b[0];
    if (d < BB){
        float acc = bterm;
        for (int e=0;e<DX;e++) acc = fmaf(c[d*DX+e], s_v2[e], acc);
        g_cq[d] = acc;
    }
}

// ---------------- kernel B: per-row dots ----------------
__global__ void kdots(const float* __restrict__ x)
{
    int gt  = blockIdx.x*blockDim.x + threadIdx.x;
    int row = gt >> 5;
    int lane = gt & 31;
    if (row >= BL) return;
    float4 xv = ((const float4*)x)[row*32 + lane];
    float4 av = ((const float4*)g_v1)[lane];
    float4 bv = ((const float4*)g_u1)[lane];
    float4 cv = ((const float4*)g_u2)[lane];
    float s0 = xv.x*av.x + xv.y*av.y + xv.z*av.z + xv.w*av.w;
    float s1 = xv.x*bv.x + xv.y*bv.y + xv.z*bv.z + xv.w*bv.w;
    float s2 = xv.x*cv.x + xv.y*cv.y + xv.z*cv.z + xv.w*cv.w;
    #pragma unroll
    for (int o=16;o;o>>=1){
        s0 += __shfl_down_sync(0xffffffffu, s0, o);
        s1 += __shfl_down_sync(0xffffffffu, s1, o);
        s2 += __shfl_down_sync(0xffffffffu, s2, o);
    }
    if (lane==0){
        g_logits[row] = s0 + g_cq[row>>12];
        g_d1[row] = s1;
        g_d2[row] = s2;
    }
}

// ---------------- kernel C: softmax + si/sjc + sjc-moments -> E ----------------
__global__ void __launch_bounds__(512) ksmE()
{
    int b = blockIdx.x, tid = threadIdx.x;
    int lane = tid & 31, wid = tid >> 5;     // 16 warps
    __shared__ float sred[16];
    __shared__ float smom[16][10];
    __shared__ float sm_bc, ss_bc;
    const float* lg = g_logits + b*LL;

    // pass 1: max
    float m = -1e30f;
    for (int i=tid;i<LL;i+=512) m = fmaxf(m, lg[i]);
    m = wrmax(m);
    if (lane==0) sred[wid]=m;
    __syncthreads();
    if (tid==0){
        float mm=sred[0];
        for (int w=1;w<16;w++) mm=fmaxf(mm,sred[w]);
        sm_bc = mm;
    }
    __syncthreads();
    m = sm_bc;

    // pass 2: sum exp
    float s=0.f;
    for (int i=tid;i<LL;i+=512) s += __expf(lg[i]-m);
    s = wradd(s);
    if (lane==0) sred[wid]=s;
    __syncthreads();
    if (tid==0){
        float t=0.f;
        for (int w=0;w<16;w++) t+=sred[w];
        ss_bc = 1.0f/t;
    }
    __syncthreads();
    float inv = ss_bc;
    float cc  = g_cconst;

    // pass 3: emit si, sjc; track ranges; accumulate sjc-moments
    float lmsi = 0.f, lmsj = 0.f;
    float mm[10];
    #pragma unroll
    for (int k=0;k<10;k++) mm[k]=0.f;
    for (int i=tid;i<LL;i+=512){
        float p = __expf(lg[i]-m)*inv;
        float si  = p*g_d1[b*LL+i];
        float sjc = fmaf(p, g_d2[b*LL+i], cc);
        g_si [b*LL+i] = si;
        g_sjc[b*LL+i] = sjc;
        lmsi = fmaxf(lmsi, fabsf(si));
        lmsj = fmaxf(lmsj, fabsf(sjc));
        float pw = 1.f;
        #pragma unroll
        for (int k=0;k<10;k++){ mm[k]+=pw; pw*=sjc; }
    }
    #pragma unroll
    for (int k=0;k<10;k++){
        float v = wradd(mm[k]);
        if (lane==0) smom[wid][k]=v;
    }
    lmsi = wrmax(lmsi); lmsj = wrmax(lmsj);
    if (lane==0){
        atomicMax(&g_msi,  __float_as_uint(lmsi));
        atomicMax(&g_msjc, __float_as_uint(lmsj));
    }
    __syncthreads();
    if (tid < 10){
        float M[10];
        #pragma unroll
        for (int k=0;k<10;k++){
            float t=0.f;
            for (int w=0;w<16;w++) t+=smom[w][k];
            M[k]=t;
        }
        float e = 0.f;
        for (int mi=0; tid+mi<10; mi++)
            e = fmaf(c_P[tid+mi]*c_BIN[tid+mi][tid], M[mi], e);
        g_E[b][tid] = e;
    }
}

// ---------------- kernel D: invZ + invZ-weighted si-moments -> F ----------------
__global__ void __launch_bounds__(512) kZF()
{
    if (!poly_ok()) return;
    int b = blockIdx.x, tid = threadIdx.x;
    int lane = tid & 31, wid = tid >> 5;
    __shared__ float sE[10];
    __shared__ float smom[16][10];
    if (tid < 10) sE[tid] = g_E[b][tid];
    __syncthreads();

    float mm[10];
    #pragma unroll
    for (int k=0;k<10;k++) mm[k]=0.f;

    for (int i=tid;i<LL;i+=512){
        float si  = g_si [b*LL+i];
        float sjc = g_sjc[b*LL+i];
        float z = sE[9];
        #pragma unroll
        for (int k=8;k>=0;k--) z = fmaf(z, si, sE[k]);
        z -= fpoly(si + sjc);
        float w = 1.0f / z;
        g_invZ[b*LL+i] = w;
        float pw = w;
        #pragma unroll
        for (int k=0;k<10;k++){ mm[k]+=pw; pw*=si; }
    }
    #pragma unroll
    for (int k=0;k<10;k++){
        float v = wradd(mm[k]);
        if (lane==0) smom[wid][k]=v;
    }
    __syncthreads();
    if (tid < 10){
        float M[10];
        #pragma unroll
        for (int k=0;k<10;k++){
            float t=0.f;
            for (int w=0;w<16;w++) t+=smom[w][k];
            M[k]=t;
        }
        float e = 0.f;
        for (int mi=0; tid+mi<10; mi++)
            e = fmaf(c_P[tid+mi]*c_BIN[tid+mi][tid], M[mi], e);
        g_F[b][tid] = e;
    }
}

// ============ MUFU FALLBACK PATH (gated) ============

__global__ void __launch_bounds__(256) kZfb()
{
    if (poly_ok()) return;
    __shared__ __align__(16) float ssj[1024];
    int b = blockIdx.z, jt = blockIdx.y, it = blockIdx.x;
    const float* sjc = g_sjc + b*LL + jt*1024;
    for (int j=threadIdx.x;j<1024;j+=256) ssj[j]=sjc[j];
    __syncthreads();
    int i = it*256 + threadIdx.x;
    float si = g_si[b*LL+i];
    float a0=0.f,a1=0.f,a2=0.f,a3=0.f;
    #pragma unroll 2
    for (int j=0;j<1024;j+=4){
        a0 += fsig(si+ssj[j+0]);
        a1 += fsig(si+ssj[j+1]);
        a2 += fsig(si+ssj[j+2]);
        a3 += fsig(si+ssj[j+3]);
    }
    g_Zpart[(b*4+jt)*LL + i] = (a0+a1)+(a2+a3);
}

__global__ void kZfbfin()
{
    if (poly_ok()) return;
    int g = blockIdx.x*blockDim.x + threadIdx.x;
    int b = g >> 12, il = g & (LL-1);
    float Z = g_Zpart[(b*4+0)*LL+il] + g_Zpart[(b*4+1)*LL+il]
            + g_Zpart[(b*4+2)*LL+il] + g_Zpart[(b*4+3)*LL+il];
    Z -= fsig(g_si[g] + g_sjc[g]);
    g_invZ[g] = 1.0f / Z;
}

__global__ void __launch_bounds__(256) kSfb()
{
    if (poly_ok()) return;
    __shared__ __align__(16) float ssi[1024];
    __shared__ __align__(16) float swz[1024];
    int b = blockIdx.z, ic = blockIdx.y, jt = blockIdx.x;
    int base = b*LL + ic*1024;
    for (int k=threadIdx.x;k<1024;k+=256){ ssi[k]=g_si[base+k]; swz[k]=g_invZ[base+k]; }
    __syncthreads();
    int j = jt*256 + threadIdx.x;
    float sj = g_sjc[b*LL+j];
    float a0=0.f,a1=0.f,a2=0.f,a3=0.f;
    #pragma unroll 2
    for (int i=0;i<1024;i+=4){
        a0 = fmaf(fsig(sj+ssi[i+0]), swz[i+0], a0);
        a1 = fmaf(fsig(sj+ssi[i+1]), swz[i+1], a1);
        a2 = fmaf(fsig(sj+ssi[i+2]), swz[i+2], a2);
        a3 = fmaf(fsig(sj+ssi[i+3]), swz[i+3], a3);
    }
    g_Spart[(b*4+ic)*LL + j] = (a0+a1)+(a2+a3);
}

__global__ void kSfbfin()
{
    if (poly_ok()) return;
    int g = blockIdx.x*blockDim.x + threadIdx.x;
    int b = g >> 12, il = g & (LL-1);
    float S = g_Spart[(b*4+0)*LL+il] + g_Spart[(b*4+1)*LL+il]
            + g_Spart[(b*4+2)*LL+il] + g_Spart[(b*4+3)*LL+il];
    S -= fsig(g_si[g] + g_sjc[g]) * g_invZ[g];
    g_S[g] = S;
}

// ---------------- kernel F: S inline -> ui -> FFN -> residual -> LayerNorm ----------------
__device__ __forceinline__ void gemm2x(const float* __restrict__ ws,
                                       const float* __restrict__ in_s,
                                       int r0, int col, ull acc[8][4])
{
    #pragma unroll 2
    for (int d=0; d<DX; d+=4){
        ull w[4][4];
        #pragma unroll
        for (int dd=0; dd<4; dd++){
            float4 wa = *(const float4*)(ws + (d+dd)*DX + col);
            float4 wb = *(const float4*)(ws + (d+dd)*DX + col + 4);
            w[dd][0]=pk2(wa.x,wa.y); w[dd][1]=pk2(wa.z,wa.w);
            w[dd][2]=pk2(wb.x,wb.y); w[dd][3]=pk2(wb.z,wb.w);
        }
        #pragma unroll
        for (int r=0; r<8; r++){
            float4 xv = *(const float4*)(in_s + (r0+r)*DX + d);
            ull x0=pk2(xv.x,xv.x), x1=pk2(xv.y,xv.y);
            ull x2=pk2(xv.z,xv.z), x3=pk2(xv.w,xv.w);
            #pragma unroll
            for (int q=0; q<4; q++){
                acc[r][q] = fma2(x0, w[0][q], acc[r][q]);
                acc[r][q] = fma2(x1, w[1][q], acc[r][q]);
                acc[r][q] = fma2(x2, w[2][q], acc[r][q]);
                acc[r][q] = fma2(x3, w[3][q], acc[r][q]);
            }
        }
    }
}

__global__ void __launch_bounds__(256) kffn(const float* __restrict__ x,
        const float* __restrict__ w1, const float* __restrict__ b1,
        const float* __restrict__ w2, const float* __restrict__ b2,
        const float* __restrict__ lng, const float* __restrict__ lnb,
        float* __restrict__ out)
{
    extern __shared__ float sm[];
    float* ws  = sm;            // 16384 floats
    float* ins = sm + 16384;    // 16384 floats
    float* hs  = sm + 32768;    // 16384 floats
    float* sS  = sm + 49152;    // 128 floats

    int tid = threadIdx.x;
    int colg = tid & 15, rowg = tid >> 4;
    int col = colg*8, r0 = rowg*8;
    int rowbase = blockIdx.x * 128;

    // phase A: per-row S (threads<128), w1 load (all threads)
    if (tid < 128){
        int gr = rowbase + tid;
        float s;
        if (poly_ok()){
            const float* F = g_F[gr>>12];
            float sj = g_sjc[gr];
            float v = F[9];
            #pragma unroll
            for (int k=8;k>=0;k--) v = fmaf(v, sj, F[k]);
            s = v - fpoly(g_si[gr] + sj) * g_invZ[gr];
        } else {
            s = g_S[gr];
        }
        sS[tid] = s;
    }
    for (int k=tid; k<4096; k+=256)
        ((float4*)ws)[k] = ((const float4*)w1)[k];
    __syncthreads();

    // phase B: ui = x*S
    const float4* xr = (const float4*)(x + (size_t)rowbase*DX);
    for (int k=tid; k<4096; k+=256){
        float s = sS[k>>5];
        float4 v = xr[k];
        v.x*=s; v.y*=s; v.z*=s; v.w*=s;
        ((float4*)ins)[k] = v;
    }
    __syncthreads();

    ull acc[8][4];

    // ---- stage 1: hidden = relu(ui @ W1 + b1) ----
    #pragma unroll
    for (int r=0;r<8;r++){ acc[r][0]=0ull; acc[r][1]=0ull; acc[r][2]=0ull; acc[r][3]=0ull; }
    gemm2x(ws, ins, r0, col, acc);
    {
        float4 bb0 = *(const float4*)(b1+col);
        float4 bb1 = *(const float4*)(b1+col+4);
        #pragma unroll
        for (int r=0;r<8;r++){
            float2 u0=upk2(acc[r][0]), u1=upk2(acc[r][1]);
            float2 u2=upk2(acc[r][2]), u3=upk2(acc[r][3]);
            float4 h0, h1;
            h0.x = fmaxf(u0.x+bb0.x, 0.f); h0.y = fmaxf(u0.y+bb0.y, 0.f);
            h0.z = fmaxf(u1.x+bb0.z, 0.f); h0.w = fmaxf(u1.y+bb0.w, 0.f);
            h1.x = fmaxf(u2.x+bb1.x, 0.f); h1.y = fmaxf(u2.y+bb1.y, 0.f);
            h1.z = fmaxf(u3.x+bb1.z, 0.f); h1.w = fmaxf(u3.y+bb1.w, 0.f);
            *(float4*)(hs + (r0+r)*DX + col)     = h0;
            *(float4*)(hs + (r0+r)*DX + col + 4) = h1;
        }
    }
    __syncthreads();

    for (int k=tid; k<4096; k+=256)
        ((float4*)ws)[k] = ((const float4*)w2)[k];
    __syncthreads();

    // ---- stage 2: y = hidden @ W2 + b2 + ui; LayerNorm; store ----
    #pragma unroll
    for (int r=0;r<8;r++){ acc[r][0]=0ull; acc[r][1]=0ull; acc[r][2]=0ull; acc[r][3]=0ull; }
    gemm2x(ws, hs, r0, col, acc);
    {
        float4 bb0 = *(const float4*)(b2+col);
        float4 bb1 = *(const float4*)(b2+col+4);
        float4 g0  = *(const float4*)(lng+col);
        float4 g1  = *(const float4*)(lng+col+4);
        float4 be0 = *(const float4*)(lnb+col);
        float4 be1 = *(const float4*)(lnb+col+4);
        #pragma unroll
        for (int r=0;r<8;r++){
            float2 u0=upk2(acc[r][0]), u1=upk2(acc[r][1]);
            float2 u2=upk2(acc[r][2]), u3=upk2(acc[r][3]);
            float4 rs0 = *(const float4*)(ins + (r0+r)*DX + col);
            float4 rs1 = *(const float4*)(ins + (r0+r)*DX + col + 4);
            float y0 = u0.x+bb0.x+rs0.x, y1 = u0.y+bb0.y+rs0.y;
            float y2 = u1.x+bb0.z+rs0.z, y3 = u1.y+bb0.w+rs0.w;
            float y4 = u2.x+bb1.x+rs1.x, y5 = u2.y+bb1.y+rs1.y;
            float y6 = u3.x+bb1.z+rs1.z, y7 = u3.y+bb1.w+rs1.w;
            float s = ((y0+y1)+(y2+y3)) + ((y4+y5)+(y6+y7));
            #pragma unroll
            for (int o=1;o<16;o<<=1) s += __shfl_xor_sync(0xffffffffu, s, o);
            float mu = s * (1.0f/128.0f);
            float d0=y0-mu,d1=y1-mu,d2=y2-mu,d3=y3-mu;
            float d4=y4-mu,d5=y5-mu,d6=y6-mu,d7=y7-mu;
            float q = ((d0*d0+d1*d1)+(d2*d2+d3*d3)) + ((d4*d4+d5*d5)+(d6*d6+d7*d7));
            #pragma unroll
            for (int o=1;o<16;o<<=1) q += __shfl_xor_sync(0xffffffffu, q, o);
            float inv = rsqrtf(q*(1.0f/128.0f) + 1e-6f);
            float4 o0, o1;
            o0.x = d0*inv*g0.x + be0.x; o0.y = d1*inv*g0.y + be0.y;
            o0.z = d2*inv*g0.z + be0.z; o0.w = d3*inv*g0.w + be0.w;
            o1.x = d4*inv*g1.x + be1.x; o1.y = d5*inv*g1.y + be1.y;
            o1.z = d6*inv*g1.z + be1.z; o1.w = d7*inv*g1.w + be1.w;
            float* orow = out + (size_t)(rowbase + r0 + r)*DX;
            *(float4*)(orow + col)     = o0;
            *(float4*)(orow + col + 4) = o1;
        }
    }
}

// ---------------- launch ----------------
extern "C" void kernel_launch(void* const* d_in, const int* in_sizes, int n_in,
                              void* d_out, int out_size)
{
    const float* x     = (const float*)d_in[0];
    const float* c     = (const float*)d_in[1];
    const float* W1    = (const float*)d_in[2];
    const float* W2    = (const float*)d_in[3];
    const float* wt_w  = (const float*)d_in[4];
    const float* bsa   = (const float*)d_in[5];
    const float* Wsa1  = (const float*)d_in[6];
    const float* Wsa2  = (const float*)d_in[7];
    const float* wsatw = (const float*)d_in[8];
    const float* wsatb = (const float*)d_in[9];
    const float* bsa1  = (const float*)d_in[10];
    const float* pw1   = (const float*)d_in[11];
    const float* pb1   = (const float*)d_in[12];
    const float* pw2   = (const float*)d_in[13];
    const float* pb2   = (const float*)d_in[14];
    const float* lng   = (const float*)d_in[15];
    const float* lnb   = (const float*)d_in[16];
    float* out = (float*)d_out;

    kprep<<<1,128>>>(W1,W2,wt_w,bsa,Wsa1,Wsa2,wsatw,wsatb,bsa1,c);
    kdots<<<(BL*32)/256,256>>>(x);
    ksmE<<<BB,512>>>();
    kZF<<<BB,512>>>();

    // MUFU fallback (early-exit when poly path valid)
    kZfb<<<dim3(16,4,BB),256>>>();
    kZfbfin<<<BL/256,256>>>();
    kSfb<<<dim3(16,4,BB),256>>>();
    kSfbfin<<<BL/256,256>>>();

    cudaFuncSetAttribute(kffn, cudaFuncAttributeMaxDynamicSharedMemorySize, 197120);
    kffn<<<BL/128,256,197120>>>(x,pw1,pb1,pw2,pb2,lng,lnb,out);
}

// round 5
// speedup vs baseline: 2.0425x; 1.0639x over previous
#include <cuda_runtime.h>

typedef unsigned long long ull;

#define BB 8
#define LL 4096
#define DX 128
#define BL (BB*LL)

// ---------------- scratch ----------------
__device__ float g_v1[DX], g_u1[DX], g_u2[DX];
__device__ float g_cq[BB];
__device__ float g_cconst;
__device__ float g_logits[BL], g_d1[BL], g_d2[BL];
__device__ float g_si[BL], g_sjc[BL];
__device__ float g_invZ[BL], g_S[BL];
__device__ float g_Zpart[BL*4], g_Spart[BL*4];
__device__ float g_Mpart[BB*8*10], g_Fpart[BB*8*10];
__device__ float g_psum[BB*8];
__device__ unsigned g_lmax[BB];
__device__ unsigned g_msi, g_msjc;   // max|si|, max|sjc| as uint bits

// ---------------- exp(sigmoid(t)) Taylor deg-9, valid |t|<=1 ----------------
#define P0f  1.64872127f
#define P1f  0.412180318f
#define P2f  0.0515225397f
#define P3f (-0.03005490f)
#define P4f (-0.00831874f)
#define P5f  0.00237489f
#define P6f  0.00112763f
#define P7f (-1.56355e-4f)
#define P8f (-1.38606e-4f)
#define P9f  5.4551e-6f

__constant__ float c_P[10] = {P0f,P1f,P2f,P3f,P4f,P5f,P6f,P7f,P8f,P9f};
__constant__ float c_BIN[10][10] = {
    {1,0,0,0,0,0,0,0,0,0},
    {1,1,0,0,0,0,0,0,0,0},
    {1,2,1,0,0,0,0,0,0,0},
    {1,3,3,1,0,0,0,0,0,0},
    {1,4,6,4,1,0,0,0,0,0},
    {1,5,10,10,5,1,0,0,0,0},
    {1,6,15,20,15,6,1,0,0,0},
    {1,7,21,35,35,21,7,1,0,0},
    {1,8,28,56,70,56,28,8,1,0},
    {1,9,36,84,126,126,84,36,9,1},
};

__device__ __forceinline__ float fpoly(float t){
    float r = P9f;
    r = fmaf(r,t,P8f); r = fmaf(r,t,P7f); r = fmaf(r,t,P6f);
    r = fmaf(r,t,P5f); r = fmaf(r,t,P4f); r = fmaf(r,t,P3f);
    r = fmaf(r,t,P2f); r = fmaf(r,t,P1f); r = fmaf(r,t,P0f);
    return r;
}

// MUFU fallback f
__device__ __forceinline__ float ex2a(float x){ float r; asm("ex2.approx.ftz.f32 %0,%1;":"=f"(r):"f"(x)); return r; }
__device__ __forceinline__ float rcpa(float x){ float r; asm("rcp.approx.ftz.f32 %0,%1;":"=f"(r):"f"(x)); return r; }
__device__ __forceinline__ float fsig(float t){
    const float L2E = 1.44269504088896f;
    float e = ex2a(t * -L2E);
    float s = rcpa(1.0f + e);
    return ex2a(s * L2E);
}

__device__ __forceinline__ bool poly_ok(){
    return (__uint_as_float(g_msi) + __uint_as_float(g_msjc)) <= 1.0f;
}

// float <-> monotone uint key (for order-independent atomic max)
__device__ __forceinline__ unsigned fkey(float f){
    unsigned u = __float_as_uint(f);
    return (u & 0x80000000u) ? ~u : (u | 0x80000000u);
}
__device__ __forceinline__ float funkey(unsigned k){
    unsigned u = (k & 0x80000000u) ? (k ^ 0x80000000u) : ~k;
    return __uint_as_float(u);
}

// ---------------- f32x2 helpers ----------------
__device__ __forceinline__ ull pk2(float x, float y){
    ull r; asm("mov.b64 %0,{%1,%2};" : "=l"(r) : "f"(x), "f"(y)); return r;
}
__device__ __forceinline__ ull fma2(ull a, ull b, ull c){
    ull d; asm("fma.rn.f32x2 %0,%1,%2,%3;" : "=l"(d) : "l"(a), "l"(b), "l"(c)); return d;
}
__device__ __forceinline__ float2 upk2(ull p){
    float2 v; asm("mov.b64 {%0,%1},%2;" : "=f"(v.x), "=f"(v.y) : "l"(p)); return v;
}

__device__ __forceinline__ float wradd(float v){
    #pragma unroll
    for (int o=16;o;o>>=1) v += __shfl_xor_sync(0xffffffffu, v, o);
    return v;
}
__device__ __forceinline__ float wrmax(float v){
    #pragma unroll
    for (int o=16;o;o>>=1) v = fmaxf(v, __shfl_xor_sync(0xffffffffu, v, o));
    return v;
}

// ---------------- kernel A: fold linear heads (512 threads, 4 mat-vecs parallel) ----------------
__global__ void __launch_bounds__(512) kprep(
                      const float* __restrict__ W1, const float* __restrict__ W2,
                      const float* __restrict__ wt_w, const float* __restrict__ bsa,
                      const float* __restrict__ Wsa1, const float* __restrict__ Wsa2,
                      const float* __restrict__ wsat_w, const float* __restrict__ wsat_b,
                      const float* __restrict__ bsa1, const float* __restrict__ c)
{
    __shared__ float s_wt[DX], s_ws[DX], s_v2[DX], s_red[DX];
    int tid = threadIdx.x;
    int d = tid & 127, mat = tid >> 7;
    if (tid < DX){ s_wt[tid]=wt_w[tid]; s_ws[tid]=wsat_w[tid]; }
    if (tid == 0){ g_msi = 0u; g_msjc = 0u; }
    if (tid < BB) g_lmax[tid] = 0u;
    __syncthreads();
    const float* W  = (mat==0)?W1:(mat==1)?W2:(mat==2)?Wsa1:Wsa2;
    const float* vv = (mat<2)? s_wt : s_ws;
    float a = 0.f;
    #pragma unroll 4
    for (int e=0;e<DX;e++) a = fmaf(W[d*DX+e], vv[e], a);
    if      (mat==0) g_v1[d]=a;
    else if (mat==1) s_v2[d]=a;
    else if (mat==2) g_u1[d]=a;
    else             g_u2[d]=a;
    if (tid < 128) s_red[tid] = bsa[tid]*s_wt[tid];
    __syncthreads();
    for (int o=64;o;o>>=1){ if(tid<o) s_red[tid]+=s_red[tid+o]; __syncthreads(); }
    float bterm = s_red[0];
    __syncthreads();
    if (tid < 128) s_red[tid] = bsa1[tid]*s_ws[tid];
    __syncthreads();
    for (int o=64;o;o>>=1){ if(tid<o) s_red[tid]+=s_red[tid+o]; __syncthreads(); }
    if (tid==0) g_cconst = s_red[0] + wsat_b[0];
    if (tid < BB){
        float acc = bterm;
        for (int e=0;e<DX;e++) acc = fmaf(c[tid*DX+e], s_v2[e], acc);
        g_cq[tid] = acc;
    }
}

// ---------------- kernel B: per-row dots + per-batch logit max ----------------
__global__ void kdots(const float* __restrict__ x)
{
    __shared__ float smax[8];
    int gt  = blockIdx.x*blockDim.x + threadIdx.x;
    int row = gt >> 5;
    int lane = gt & 31;
    float4 xv = ((const float4*)x)[row*32 + lane];
    float4 av = ((const float4*)g_v1)[lane];
    float4 bv = ((const float4*)g_u1)[lane];
    float4 cv = ((const float4*)g_u2)[lane];
    float s0 = xv.x*av.x + xv.y*av.y + xv.z*av.z + xv.w*av.w;
    float s1 = xv.x*bv.x + xv.y*bv.y + xv.z*bv.z + xv.w*bv.w;
    float s2 = xv.x*cv.x + xv.y*cv.y + xv.z*cv.z + xv.w*cv.w;
    #pragma unroll
    for (int o=16;o;o>>=1){
        s0 += __shfl_down_sync(0xffffffffu, s0, o);
        s1 += __shfl_down_sync(0xffffffffu, s1, o);
        s2 += __shfl_down_sync(0xffffffffu, s2, o);
    }
    if (lane==0){
        float l = s0 + g_cq[row>>12];
        g_logits[row] = l;
        g_d1[row] = s1;
        g_d2[row] = s2;
        smax[threadIdx.x>>5] = l;
    }
    __syncthreads();
    if (threadIdx.x==0){
        float m = smax[0];
        #pragma unroll
        for (int w=1;w<8;w++) m = fmaxf(m, smax[w]);
        atomicMax(&g_lmax[(blockIdx.x*8)>>12], fkey(m));   // no return -> REDG
    }
}

// ---------------- kernel C: partial softmax sums (grid 8 slices x 8 batches) ----------------
__global__ void __launch_bounds__(512) kPS()
{
    int s = blockIdx.x, b = blockIdx.y, tid = threadIdx.x;
    __shared__ float sred[16];
    float m = funkey(g_lmax[b]);
    float v = __expf(g_logits[b*LL + s*512 + tid] - m);
    v = wradd(v);
    if ((tid&31)==0) sred[tid>>5] = v;
    __syncthreads();
    if (tid==0){
        float t = 0.f;
        #pragma unroll
        for (int w=0;w<16;w++) t += sred[w];
        g_psum[b*8+s] = t;
    }
}

// ---------------- kernel D: si/sjc + partial sjc-moments + ranges ----------------
__global__ void __launch_bounds__(512) kE()
{
    int s = blockIdx.x, b = blockIdx.y, tid = threadIdx.x;
    int lane = tid & 31, wid = tid >> 5;
    __shared__ float smom[16][10];
    int idx = b*LL + s*512 + tid;
    float m = funkey(g_lmax[b]);
    float t = 0.f;
    #pragma unroll
    for (int k=0;k<8;k++) t += g_psum[b*8+k];
    float inv = 1.0f/t;
    float cc = g_cconst;
    float p = __expf(g_logits[idx]-m)*inv;
    float si  = p*g_d1[idx];
    float sjc = fmaf(p, g_d2[idx], cc);
    g_si[idx]=si; g_sjc[idx]=sjc;
    float rs = wrmax(fabsf(si)), rj = wrmax(fabsf(sjc));
    if (lane==0){
        atomicMax(&g_msi,  __float_as_uint(rs));
        atomicMax(&g_msjc, __float_as_uint(rj));
    }
    float pw = 1.f;
    #pragma unroll
    for (int k=0;k<10;k++){
        float v = wradd(pw);
        if (lane==0) smom[wid][k]=v;
        pw *= sjc;
    }
    __syncthreads();
    if (tid < 10){
        float acc = 0.f;
        #pragma unroll
        for (int w=0;w<16;w++) acc += smom[w][tid];
        g_Mpart[(b*8+s)*10 + tid] = acc;
    }
}

// ---------------- kernel E: invZ + partial invZ-weighted si-moments ----------------
__global__ void __launch_bounds__(512) kZF()
{
    if (!poly_ok()) return;
    int s = blockIdx.x, b = blockIdx.y, tid = threadIdx.x;
    int lane = tid & 31, wid = tid >> 5;
    __shared__ float sE[10];
    __shared__ float smom[16][10];
    if (tid < 10){
        float M[10];
        #pragma unroll
        for (int mi=0;mi<10;mi++){
            float acc = 0.f;
            #pragma unroll
            for (int ss=0;ss<8;ss++) acc += g_Mpart[(b*8+ss)*10 + mi];
            M[mi] = acc;
        }
        float e = 0.f;
        for (int mi=0; tid+mi<10; mi++)
            e = fmaf(c_P[tid+mi]*c_BIN[tid+mi][tid], M[mi], e);
        sE[tid] = e;
    }
    __syncthreads();
    int idx = b*LL + s*512 + tid;
    float si = g_si[idx], sjc = g_sjc[idx];
    float z = sE[9];
    #pragma unroll
    for (int k=8;k>=0;k--) z = fmaf(z, si, sE[k]);
    z -= fpoly(si + sjc);
    float w = 1.0f / z;
    g_invZ[idx] = w;
    float pw = w;
    #pragma unroll
    for (int k=0;k<10;k++){
        float v = wradd(pw);
        if (lane==0) smom[wid][k]=v;
        pw *= si;
    }
    __syncthreads();
    if (tid < 10){
        float acc = 0.f;
        #pragma unroll
        for (int ww=0;ww<16;ww++) acc += smom[ww][tid];
        g_Fpart[(b*8+s)*10 + tid] = acc;
    }
}

// ============ MUFU FALLBACK PATH (gated) ============

__global__ void __launch_bounds__(256) kZfb()
{
    if (poly_ok()) return;
    __shared__ __align__(16) float ssj[1024];
    int b = blockIdx.z, jt = blockIdx.y, it = blockIdx.x;
    const float* sjc = g_sjc + b*LL + jt*1024;
    for (int j=threadIdx.x;j<1024;j+=256) ssj[j]=sjc[j];
    __syncthreads();
    int i = it*256 + threadIdx.x;
    float si = g_si[b*LL+i];
    float a0=0.f,a1=0.f,a2=0.f,a3=0.f;
    #pragma unroll 2
    for (int j=0;j<1024;j+=4){
        a0 += fsig(si+ssj[j+0]);
        a1 += fsig(si+ssj[j+1]);
        a2 += fsig(si+ssj[j+2]);
        a3 += fsig(si+ssj[j+3]);
    }
    g_Zpart[(b*4+jt)*LL + i] = (a0+a1)+(a2+a3);
}

__global__ void kZfbfin()
{
    if (poly_ok()) return;
    int g = blockIdx.x*blockDim.x + threadIdx.x;
    int b = g >> 12, il = g & (LL-1);
    float Z = g_Zpart[(b*4+0)*LL+il] + g_Zpart[(b*4+1)*LL+il]
            + g_Zpart[(b*4+2)*LL+il] + g_Zpart[(b*4+3)*LL+il];
    Z -= fsig(g_si[g] + g_sjc[g]);
    g_invZ[g] = 1.0f / Z;
}

__global__ void __launch_bounds__(256) kSfb()
{
    if (poly_ok()) return;
    __shared__ __align__(16) float ssi[1024];
    __shared__ __align__(16) float swz[1024];
    int b = blockIdx.z, ic = blockIdx.y, jt = blockIdx.x;
    int base = b*LL + ic*1024;
    for (int k=threadIdx.x;k<1024;k+=256){ ssi[k]=g_si[base+k]; swz[k]=g_invZ[base+k]; }
    __syncthreads();
    int j = jt*256 + threadIdx.x;
    float sj = g_sjc[b*LL+j];
    float a0=0.f,a1=0.f,a2=0.f,a3=0.f;
    #pragma unroll 2
    for (int i=0;i<1024;i+=4){
        a0 = fmaf(fsig(sj+ssi[i+0]), swz[i+0], a0);
        a1 = fmaf(fsig(sj+ssi[i+1]), swz[i+1], a1);
        a2 = fmaf(fsig(sj+ssi[i+2]), swz[i+2], a2);
        a3 = fmaf(fsig(sj+ssi[i+3]), swz[i+3], a3);
    }
    g_Spart[(b*4+ic)*LL + j] = (a0+a1)+(a2+a3);
}

__global__ void kSfbfin()
{
    if (poly_ok()) return;
    int g = blockIdx.x*blockDim.x + threadIdx.x;
    int b = g >> 12, il = g & (LL-1);
    float S = g_Spart[(b*4+0)*LL+il] + g_Spart[(b*4+1)*LL+il]
            + g_Spart[(b*4+2)*LL+il] + g_Spart[(b*4+3)*LL+il];
    S -= fsig(g_si[g] + g_sjc[g]) * g_invZ[g];
    g_S[g] = S;
}

// ---------------- kernel F: F+S inline -> ui -> FFN -> residual -> LayerNorm ----------------
__device__ __forceinline__ void gemm2x(const float* __restrict__ ws,
                                       const float* __restrict__ in_s,
                                       int r0, int col, ull acc[8][4])
{
    #pragma unroll 2
    for (int d=0; d<DX; d+=4){
        ull w[4][4];
        #pragma unroll
        for (int dd=0; dd<4; dd++){
            float4 wa = *(const float4*)(ws + (d+dd)*DX + col);
            float4 wb = *(const float4*)(ws + (d+dd)*DX + col + 4);
            w[dd][0]=pk2(wa.x,wa.y); w[dd][1]=pk2(wa.z,wa.w);
            w[dd][2]=pk2(wb.x,wb.y); w[dd][3]=pk2(wb.z,wb.w);
        }
        #pragma unroll
        for (int r=0; r<8; r++){
            float4 xv = *(const float4*)(in_s + (r0+r)*DX + d);
            ull x0=pk2(xv.x,xv.x), x1=pk2(xv.y,xv.y);
            ull x2=pk2(xv.z,xv.z), x3=pk2(xv.w,xv.w);
            #pragma unroll
            for (int q=0; q<4; q++){
                acc[r][q] = fma2(x0, w[0][q], acc[r][q]);
                acc[r][q] = fma2(x1, w[1][q], acc[r][q]);
                acc[r][q] = fma2(x2, w[2][q], acc[r][q]);
                acc[r][q] = fma2(x3, w[3][q], acc[r][q]);
            }
        }
    }
}

__global__ void __launch_bounds__(256) kffn(const float* __restrict__ x,
        const float* __restrict__ w1, const float* __restrict__ b1,
        const float* __restrict__ w2, const float* __restrict__ b2,
        const float* __restrict__ lng, const float* __restrict__ lnb,
        float* __restrict__ out)
{
    extern __shared__ float sm[];
    float* ws  = sm;            // 16384 floats
    float* ins = sm + 16384;    // 16384 floats
    float* hs  = sm + 32768;    // 16384 floats
    float* sS  = sm + 49152;    // 128 floats
    float* sF  = sm + 49280;    // 10 floats

    int tid = threadIdx.x;
    int colg = tid & 15, rowg = tid >> 4;
    int col = colg*8, r0 = rowg*8;
    int rowbase = blockIdx.x * 128;
    int b = rowbase >> 12;
    bool pok = poly_ok();

    // phase A0: derive F for this batch (redundant per block, trivial)
    if (pok && tid < 10){
        float M[10];
        #pragma unroll
        for (int mi=0;mi<10;mi++){
            float acc = 0.f;
            #pragma unroll
            for (int ss=0;ss<8;ss++) acc += g_Fpart[(b*8+ss)*10 + mi];
            M[mi] = acc;
        }
        float e = 0.f;
        for (int mi=0; tid+mi<10; mi++)
            e = fmaf(c_P[tid+mi]*c_BIN[tid+mi][tid], M[mi], e);
        sF[tid] = e;
    }
    for (int k=tid; k<4096; k+=256)
        ((float4*)ws)[k] = ((const float4*)w1)[k];
    __syncthreads();

    // phase A1: per-row S
    if (tid < 128){
        int gr = rowbase + tid;
        float s;
        if (pok){
            float sj = g_sjc[gr];
            float v = sF[9];
            #pragma unroll
            for (int k=8;k>=0;k--) v = fmaf(v, sj, sF[k]);
            s = v - fpoly(g_si[gr] + sj) * g_invZ[gr];
        } else {
            s = g_S[gr];
        }
        sS[tid] = s;
    }
    __syncthreads();

    // phase B: ui = x*S
    const float4* xr = (const float4*)(x + (size_t)rowbase*DX);
    for (int k=tid; k<4096; k+=256){
        float s = sS[k>>5];
        float4 v = xr[k];
        v.x*=s; v.y*=s; v.z*=s; v.w*=s;
        ((float4*)ins)[k] = v;
    }
    __syncthreads();

    ull acc[8][4];

    // ---- stage 1: hidden = relu(ui @ W1 + b1) ----
    #pragma unroll
    for (int r=0;r<8;r++){ acc[r][0]=0ull; acc[r][1]=0ull; acc[r][2]=0ull; acc[r][3]=0ull; }
    gemm2x(ws, ins, r0, col, acc);
    {
        float4 bb0 = *(const float4*)(b1+col);
        float4 bb1 = *(const float4*)(b1+col+4);
        #pragma unroll
        for (int r=0;r<8;r++){
            float2 u0=upk2(acc[r][0]), u1=upk2(acc[r][1]);
            float2 u2=upk2(acc[r][2]), u3=upk2(acc[r][3]);
            float4 h0, h1;
            h0.x = fmaxf(u0.x+bb0.x, 0.f); h0.y = fmaxf(u0.y+bb0.y, 0.f);
            h0.z = fmaxf(u1.x+bb0.z, 0.f); h0.w = fmaxf(u1.y+bb0.w, 0.f);
            h1.x = fmaxf(u2.x+bb1.x, 0.f); h1.y = fmaxf(u2.y+bb1.y, 0.f);
            h1.z = fmaxf(u3.x+bb1.z, 0.f); h1.w = fmaxf(u3.y+bb1.w, 0.f);
            *(float4*)(hs + (r0+r)*DX + col)     = h0;
            *(float4*)(hs + (r0+r)*DX + col + 4) = h1;
        }
    }
    __syncthreads();

    for (int k=tid; k<4096; k+=256)
        ((float4*)ws)[k] = ((const float4*)w2)[k];
    __syncthreads();

    // ---- stage 2: y = hidden @ W2 + b2 + ui; LayerNorm; store ----
    #pragma unroll
    for (int r=0;r<8;r++){ acc[r][0]=0ull; acc[r][1]=0ull; acc[r][2]=0ull; acc[r][3]=0ull; }
    gemm2x(ws, hs, r0, col, acc);
    {
        float4 bb0 = *(const float4*)(b2+col);
        float4 bb1 = *(const float4*)(b2+col+4);
        float4 g0  = *(const float4*)(lng+col);
        float4 g1  = *(const float4*)(lng+col+4);
        float4 be0 = *(const float4*)(lnb+col);
        float4 be1 = *(const float4*)(lnb+col+4);
        #pragma unroll
        for (int r=0;r<8;r++){
            float2 u0=upk2(acc[r][0]), u1=upk2(acc[r][1]);
            float2 u2=upk2(acc[r][2]), u3=upk2(acc[r][3]);
            float4 rs0 = *(const float4*)(ins + (r0+r)*DX + col);
            float4 rs1 = *(const float4*)(ins + (r0+r)*DX + col + 4);
            float y0 = u0.x+bb0.x+rs0.x, y1 = u0.y+bb0.y+rs0.y;
            float y2 = u1.x+bb0.z+rs0.z, y3 = u1.y+bb0.w+rs0.w;
            float y4 = u2.x+bb1.x+rs1.x, y5 = u2.y+bb1.y+rs1.y;
            float y6 = u3.x+bb1.z+rs1.z, y7 = u3.y+bb1.w+rs1.w;
            float s = ((y0+y1)+(y2+y3)) + ((y4+y5)+(y6+y7));
            #pragma unroll
            for (int o=1;o<16;o<<=1) s += __shfl_xor_sync(0xffffffffu, s, o);
            float mu = s * (1.0f/128.0f);
            float d0=y0-mu,d1=y1-mu,d2=y2-mu,d3=y3-mu;
            float d4=y4-mu,d5=y5-mu,d6=y6-mu,d7=y7-mu;
            float q = ((d0*d0+d1*d1)+(d2*d2+d3*d3)) + ((d4*d4+d5*d5)+(d6*d6+d7*d7));
            #pragma unroll
            for (int o=1;o<16;o<<=1) q += __shfl_xor_sync(0xffffffffu, q, o);
            float inv = rsqrtf(q*(1.0f/128.0f) + 1e-6f);
            float4 o0, o1;
            o0.x = d0*inv*g0.x + be0.x; o0.y = d1*inv*g0.y + be0.y;
            o0.z = d2*inv*g0.z + be0.z; o0.w = d3*inv*g0.w + be0.w;
            o1.x = d4*inv*g1.x + be1.x; o1.y = d5*inv*g1.y + be1.y;
            o1.z = d6*inv*g1.z + be1.z; o1.w = d7*inv*g1.w + be1.w;
            float* orow = out + (size_t)(rowbase + r0 + r)*DX;
            *(float4*)(orow + col)     = o0;
            *(float4*)(orow + col + 4) = o1;
        }
    }
}

// ---------------- launch ----------------
extern "C" void kernel_launch(void* const* d_in, const int* in_sizes, int n_in,
                              void* d_out, int out_size)
{
    const float* x     = (const float*)d_in[0];
    const float* c     = (const float*)d_in[1];
    const float* W1    = (const float*)d_in[2];
    const float* W2    = (const float*)d_in[3];
    const float* wt_w  = (const float*)d_in[4];
    const float* bsa   = (const float*)d_in[5];
    const float* Wsa1  = (const float*)d_in[6];
    const float* Wsa2  = (const float*)d_in[7];
    const float* wsatw = (const float*)d_in[8];
    const float* wsatb = (const float*)d_in[9];
    const float* bsa1  = (const float*)d_in[10];
    const float* pw1   = (const float*)d_in[11];
    const float* pb1   = (const float*)d_in[12];
    const float* pw2   = (const float*)d_in[13];
    const float* pb2   = (const float*)d_in[14];
    const float* lng   = (const float*)d_in[15];
    const float* lnb   = (const float*)d_in[16];
    float* out = (float*)d_out;

    kprep<<<1,512>>>(W1,W2,wt_w,bsa,Wsa1,Wsa2,wsatw,wsatb,bsa1,c);
    kdots<<<(BL*32)/256,256>>>(x);
    kPS<<<dim3(8,BB),512>>>();
    kE<<<dim3(8,BB),512>>>();
    kZF<<<dim3(8,BB),512>>>();

    // MUFU fallback (early-exit when poly path valid)
    kZfb<<<dim3(16,4,BB),256>>>();
    kZfbfin<<<BL/256,256>>>();
    kSfb<<<dim3(16,4,BB),256>>>();
    kSfbfin<<<BL/256,256>>>();

    cudaFuncSetAttribute(kffn, cudaFuncAttributeMaxDynamicSharedMemorySize, 197632);
    kffn<<<BL/128,256,197632>>>(x,pw1,pb1,pw2,pb2,lng,lnb,out);
}